// round 11
// baseline (speedup 1.0000x reference)
#include <cuda_runtime.h>
#include <cuda_fp16.h>
#include <math.h>
#include <stdint.h>

#define BDIM 1024
#define SEQ  2048
#define NH   16
#define DKH  64
#define HIDN 4096
#define MROWS 4096   // B*S
#define NB   2

typedef __half fp16;

// ---------------- scratch (static device globals; no allocation) ----------------
__device__ float g_s1 [MROWS * BDIM];
__device__ float g_x1 [MROWS * BDIM];
__device__ float g_s2 [MROWS * BDIM];

__device__ fp16 g_xh  [MROWS * BDIM];
__device__ fp16 g_yh  [MROWS * BDIM];
__device__ fp16 g_Qh  [MROWS * BDIM];   // [B,H,S,DK]
__device__ fp16 g_Kh  [MROWS * BDIM];
__device__ fp16 g_Vh  [MROWS * BDIM];
__device__ fp16 g_ah  [MROWS * BDIM];   // attention output [B,S,D]
__device__ fp16 g_x1h [MROWS * BDIM];
__device__ fp16 g_hh  [MROWS * HIDN];

// transposed weights: Wt[N][K] fp16
__device__ fp16 g_wqT[BDIM * BDIM];
__device__ fp16 g_wkT[BDIM * BDIM];
__device__ fp16 g_wvT[BDIM * BDIM];
__device__ fp16 g_woT[BDIM * BDIM];
__device__ fp16 g_w1T[HIDN * BDIM];
__device__ fp16 g_w2T[BDIM * HIDN];

enum { MODE_RELU_H = 1, MODE_RES = 2, MODE_SPLIT_H = 4 };

// ======================= PTX helpers =======================
__device__ __forceinline__ uint32_t smem_u32(const void* p) {
    uint32_t a;
    asm("{ .reg .u64 t; cvta.to.shared.u64 t, %1; cvt.u32.u64 %0, t; }" : "=r"(a) : "l"(p));
    return a;
}
__device__ __forceinline__ void cp16(uint32_t s, const void* g) {
    asm volatile("cp.async.cg.shared.global [%0], [%1], 16;" :: "r"(s), "l"(g));
}
#define CP_COMMIT() asm volatile("cp.async.commit_group;" ::: "memory")
#define CP_WAIT0()  asm volatile("cp.async.wait_group 0;" ::: "memory")
#define CP_WAIT1()  asm volatile("cp.async.wait_group 1;" ::: "memory")
#define CP_WAIT2()  asm volatile("cp.async.wait_group 2;" ::: "memory")

__device__ __forceinline__ void ldm_x4(uint32_t& r0, uint32_t& r1, uint32_t& r2, uint32_t& r3, uint32_t a) {
    asm volatile("ldmatrix.sync.aligned.m8n8.x4.shared.b16 {%0,%1,%2,%3}, [%4];"
                 : "=r"(r0), "=r"(r1), "=r"(r2), "=r"(r3) : "r"(a));
}
__device__ __forceinline__ void ldm_x4_t(uint32_t& r0, uint32_t& r1, uint32_t& r2, uint32_t& r3, uint32_t a) {
    asm volatile("ldmatrix.sync.aligned.m8n8.x4.trans.shared.b16 {%0,%1,%2,%3}, [%4];"
                 : "=r"(r0), "=r"(r1), "=r"(r2), "=r"(r3) : "r"(a));
}
__device__ __forceinline__ void mma16816(float* c, const uint32_t* a, const uint32_t* b) {
    asm volatile("mma.sync.aligned.m16n8k16.row.col.f32.f16.f16.f32 "
                 "{%0,%1,%2,%3}, {%4,%5,%6,%7}, {%8,%9}, {%0,%1,%2,%3};"
                 : "+f"(c[0]), "+f"(c[1]), "+f"(c[2]), "+f"(c[3])
                 : "r"(a[0]), "r"(a[1]), "r"(a[2]), "r"(a[3]), "r"(b[0]), "r"(b[1]));
}
__device__ __forceinline__ uint32_t cvt2(float a, float b) {
    __half2 t = __floats2half2_rn(a, b);
    return *(uint32_t*)&t;
}

// ======================= mma.sync fp16 GEMM: 4 warps, warp tile 64x64 =======================
// C[M,N] = A[M,K] @ Wt[N,K]^T, fp32 accum.
// CTA 128x128, BK=32, 128 threads = 4 warps (2 M x 2 N), 3-stage cp.async pipeline.
#define BK 32
#define APAD 40
#define TILE_B (128 * APAD * 2)        // 10240 B
#define SLAB_B (2 * TILE_B)            // A, B
#define GEMM_SMEM (3 * SLAB_B)         // 61440 B (3 stages)

__global__ __launch_bounds__(128, 2) void mma_gemm(
    const fp16* __restrict__ A, const fp16* __restrict__ B,
    const float* __restrict__ bias, const float* __restrict__ R,
    float* __restrict__ outF, fp16* __restrict__ outH,
    int M, int N, int K, int mode)
{
    extern __shared__ char sm[];
    const uint32_t smb = smem_u32(sm);
    const int tid = threadIdx.x;
    const int wid = tid >> 5;
    const int lid = tid & 31;
    const int warp_m = wid >> 1;        // 0..1
    const int warp_n = wid & 1;         // 0..1
    const int row0 = blockIdx.y * 128;
    const int col0 = blockIdx.x * 128;

    const fp16* src[2];
    src[0] = A + (size_t)row0 * K;
    src[1] = B + (size_t)col0 * K;

    const int NS = K / BK;

#define LOAD_SLAB(ST, KS) do {                                                \
        const uint32_t _sb = smb + (ST) * SLAB_B;                             \
        const int _ko = (KS) * BK;                                            \
        _Pragma("unroll")                                                     \
        for (int t = 0; t < 2; t++) {                                         \
            const fp16* g = src[t] + _ko;                                     \
            const uint32_t tb = _sb + t * TILE_B;                             \
            _Pragma("unroll")                                                 \
            for (int u = 0; u < 4; u++) {                                     \
                int p = tid + u * 128;                                        \
                int r = p >> 2, c = p & 3;                                    \
                cp16(tb + (uint32_t)(r * (APAD * 2) + c * 16),                \
                     g + (size_t)r * K + c * 8);                              \
            }                                                                 \
        }                                                                     \
        CP_COMMIT();                                                          \
    } while (0)

    float acc[4][8][4];
#pragma unroll
    for (int i = 0; i < 4; i++)
#pragma unroll
        for (int j = 0; j < 8; j++)
#pragma unroll
            for (int f = 0; f < 4; f++) acc[i][j][f] = 0.f;

    LOAD_SLAB(0, 0);
    LOAD_SLAB(1, 1);   // K >= 1024 always => NS >= 32

    const uint32_t lrow = (uint32_t)(lid & 15);
    const uint32_t lcol16 = (uint32_t)(lid >> 4) * 16;

    int st = 0;
    for (int s = 0; s < NS; s++) {
        if (s + 2 < NS) { LOAD_SLAB((st + 2) % 3, s + 2); CP_WAIT2(); }
        else if (s + 1 < NS) { CP_WAIT1(); }
        else { CP_WAIT0(); }
        __syncthreads();

        const uint32_t ab = smb + st * SLAB_B;
        const uint32_t bb = ab + TILE_B;

#pragma unroll
        for (int kk = 0; kk < 2; kk++) {
            const uint32_t koff = kk * 32 + lcol16;

            uint32_t af[4][4];
#pragma unroll
            for (int mi = 0; mi < 4; mi++) {
                uint32_t ra = (uint32_t)((warp_m * 64 + mi * 16 + lrow) * (APAD * 2)) + koff;
                ldm_x4(af[mi][0], af[mi][1], af[mi][2], af[mi][3], ab + ra);
            }
            uint32_t bf[8][2];
#pragma unroll
            for (int nt = 0; nt < 4; nt++) {
                uint32_t rb = (uint32_t)((warp_n * 64 + nt * 16 + lrow) * (APAD * 2)) + koff;
                uint32_t r0, r1, r2, r3;
                ldm_x4(r0, r1, r2, r3, bb + rb);
                bf[nt * 2 + 0][0] = r0; bf[nt * 2 + 0][1] = r2;
                bf[nt * 2 + 1][0] = r1; bf[nt * 2 + 1][1] = r3;
            }
#pragma unroll
            for (int mi = 0; mi < 4; mi++)
#pragma unroll
                for (int ni = 0; ni < 8; ni++)
                    mma16816(acc[mi][ni], af[mi], bf[ni]);
        }
        __syncthreads();
        st = (st + 1) % 3;
    }

    // ---- epilogue ----
    const int qr = lid >> 2;
    const int qc = (lid & 3) * 2;
#pragma unroll
    for (int mi = 0; mi < 4; mi++) {
#pragma unroll
        for (int ni = 0; ni < 8; ni++) {
            const int n = col0 + warp_n * 64 + ni * 8 + qc;
            const float b0 = bias[n], b1 = bias[n + 1];
#pragma unroll
            for (int half = 0; half < 2; half++) {
                const int m = row0 + warp_m * 64 + mi * 16 + qr + half * 8;
                float v0 = acc[mi][ni][half * 2 + 0] + b0;
                float v1 = acc[mi][ni][half * 2 + 1] + b1;
                if (mode == MODE_RES) {
                    const float* rp = &R[(size_t)m * N + n];
                    v0 += rp[0]; v1 += rp[1];
                    float2 o2 = {v0, v1};
                    *(float2*)&outF[(size_t)m * N + n] = o2;
                } else if (mode == MODE_SPLIT_H) {
                    int hh = n >> 6, dk = n & 63, bb = m >> 11, ss = m & 2047;
                    size_t o = (((size_t)(bb * NH + hh)) * SEQ + ss) * DKH + dk;
                    *(__half2*)&outH[o] = __floats2half2_rn(v0, v1);
                } else { // MODE_RELU_H
                    v0 = fmaxf(v0, 0.f); v1 = fmaxf(v1, 0.f);
                    *(__half2*)&outH[(size_t)m * N + n] = __floats2half2_rn(v0, v1);
                }
            }
        }
    }
}

// ======================= tensor-core flash attention (fp16, single-pass) =======================
// Q/K/V single fp16, all [B,H,S,DK]. CTA = 128 queries x 1 head.
// 8 warps x 16 queries, KV tile 64 double-buffered. 2 CTAs/SM.
#define AT_STRIDE 144
#define AT_TILE   (64 * AT_STRIDE)            // 9216 B per 64x64 fp16 tile
#define AT_STAGE  (2 * AT_TILE)               // K, V
#define AT_MSK    (2 * AT_STAGE)              // 36864
#define AT_SMEM   (AT_MSK + 512)

__global__ __launch_bounds__(256, 2) void attn_tc(
    const fp16* __restrict__ Qg, const fp16* __restrict__ Kg,
    const fp16* __restrict__ Vg, const int* __restrict__ mask,
    fp16* __restrict__ O_out)
{
    extern __shared__ char sm[];
    const uint32_t smb = smem_u32(sm);
    const int tid = threadIdx.x;
    const int wid = tid >> 5;
    const int lid = tid & 31;
    const int q0  = blockIdx.x * 128;
    const int h   = blockIdx.y;
    const int bz  = blockIdx.z;
    const size_t hoff = ((size_t)(bz * NH + h)) * SEQ * DKH;

    const uint32_t lr   = (uint32_t)(lid & 15);
    const uint32_t lc16 = (uint32_t)(lid >> 4) * 16;

    // ---- Q tile -> smem, then register fragments ----
    {
        const fp16* qh = Qg + hoff + (size_t)q0 * DKH;
#pragma unroll
        for (int u = 0; u < 4; u++) {
            int p = tid + u * 256;
            int r = p >> 3, c = p & 7;
            cp16(smb + (uint32_t)(r * AT_STRIDE + c * 16), qh + (size_t)r * DKH + c * 8);
        }
        CP_COMMIT(); CP_WAIT0();
    }
    __syncthreads();
    uint32_t qf[4][4];
#pragma unroll
    for (int ks = 0; ks < 4; ks++) {
        uint32_t ra = (uint32_t)((wid * 16 + lr) * AT_STRIDE) + ks * 32 + lc16;
        ldm_x4(qf[ks][0], qf[ks][1], qf[ks][2], qf[ks][3], smb + ra);
    }
    __syncthreads();

    float O[8][4];
#pragma unroll
    for (int i = 0; i < 8; i++)
#pragma unroll
        for (int j = 0; j < 4; j++) O[i][j] = 0.f;
    float m0 = -INFINITY, m1 = -INFINITY, l0 = 0.f, l1 = 0.f;

    const fp16* kg = Kg + hoff;
    const fp16* vg = Vg + hoff;
    const int*  mkg = mask + bz * SEQ;

#define LOAD_KV(ST, T) do {                                                     \
        const uint32_t _sb = smb + (ST) * AT_STAGE;                             \
        const int _k0 = (T) * 64;                                               \
        _Pragma("unroll")                                                       \
        for (int u = 0; u < 2; u++) {                                           \
            int p = tid + u * 256;                                              \
            int r = p >> 3, c = p & 7;                                          \
            uint32_t so = (uint32_t)(r * AT_STRIDE + c * 16);                   \
            size_t go = (size_t)(_k0 + r) * DKH + c * 8;                        \
            cp16(_sb + so, kg + go);                                            \
            cp16(_sb + AT_TILE + so, vg + go);                                  \
        }                                                                       \
        if (tid < 16) cp16(smb + AT_MSK + (ST) * 256 + tid * 16, mkg + _k0 + tid * 4); \
        CP_COMMIT();                                                            \
    } while (0)

    LOAD_KV(0, 0);

    for (int t = 0; t < SEQ / 64; t++) {
        const int st = t & 1;
        if (t + 1 < SEQ / 64) { LOAD_KV(st ^ 1, t + 1); CP_WAIT1(); }
        else                  { CP_WAIT0(); }
        __syncthreads();

        const uint32_t sb = smb + st * AT_STAGE;
        const int* msk = (const int*)(sm + AT_MSK + st * 256);

        // ---- scores: single-pass QK^T ----
        float s[8][4];
#pragma unroll
        for (int i = 0; i < 8; i++)
#pragma unroll
            for (int j = 0; j < 4; j++) s[i][j] = 0.f;

#pragma unroll
        for (int ks = 0; ks < 4; ks++) {
            const uint32_t koff = ks * 32 + lc16;
#pragma unroll
            for (int g = 0; g < 4; g++) {
                uint32_t rb = (uint32_t)((g * 16 + lr) * AT_STRIDE) + koff;
                uint32_t r0, r1, r2, r3;
                ldm_x4(r0, r1, r2, r3, sb + rb);
                uint32_t b0[2] = {r0, r2}, b1[2] = {r1, r3};
                mma16816(s[2 * g],     qf[ks], b0);
                mma16816(s[2 * g + 1], qf[ks], b1);
            }
        }

        // ---- mask + scale ----
#pragma unroll
        for (int j = 0; j < 8; j++) {
            int c0 = j * 8 + (lid & 3) * 2;
            bool z0 = (msk[c0] == 0), z1 = (msk[c0 + 1] == 0);
            s[j][0] = z0 ? -1e9f : s[j][0] * 0.125f;
            s[j][2] = z0 ? -1e9f : s[j][2] * 0.125f;
            s[j][1] = z1 ? -1e9f : s[j][1] * 0.125f;
            s[j][3] = z1 ? -1e9f : s[j][3] * 0.125f;
        }

        // ---- online softmax (rows r and r+8) ----
        float mx0 = -INFINITY, mx1 = -INFINITY;
#pragma unroll
        for (int j = 0; j < 8; j++) {
            mx0 = fmaxf(mx0, fmaxf(s[j][0], s[j][1]));
            mx1 = fmaxf(mx1, fmaxf(s[j][2], s[j][3]));
        }
#pragma unroll
        for (int off = 1; off <= 2; off <<= 1) {
            mx0 = fmaxf(mx0, __shfl_xor_sync(0xffffffffu, mx0, off));
            mx1 = fmaxf(mx1, __shfl_xor_sync(0xffffffffu, mx1, off));
        }
        float nm0 = fmaxf(m0, mx0), nm1 = fmaxf(m1, mx1);
        float a0 = __expf(m0 - nm0), a1 = __expf(m1 - nm1);
        float sum0 = 0.f, sum1 = 0.f;
#pragma unroll
        for (int j = 0; j < 8; j++) {
            s[j][0] = __expf(s[j][0] - nm0); sum0 += s[j][0];
            s[j][1] = __expf(s[j][1] - nm0); sum0 += s[j][1];
            s[j][2] = __expf(s[j][2] - nm1); sum1 += s[j][2];
            s[j][3] = __expf(s[j][3] - nm1); sum1 += s[j][3];
        }
#pragma unroll
        for (int off = 1; off <= 2; off <<= 1) {
            sum0 += __shfl_xor_sync(0xffffffffu, sum0, off);
            sum1 += __shfl_xor_sync(0xffffffffu, sum1, off);
        }
        l0 = l0 * a0 + sum0;
        l1 = l1 * a1 + sum1;
        m0 = nm0; m1 = nm1;
#pragma unroll
        for (int i = 0; i < 8; i++) {
            O[i][0] *= a0; O[i][1] *= a0;
            O[i][2] *= a1; O[i][3] *= a1;
        }

        // ---- O += P @ V (P from registers, V via ldmatrix.trans) ----
#pragma unroll
        for (int j = 0; j < 4; j++) {
            uint32_t P[4];
            P[0] = cvt2(s[2 * j][0],     s[2 * j][1]);
            P[1] = cvt2(s[2 * j][2],     s[2 * j][3]);
            P[2] = cvt2(s[2 * j + 1][0], s[2 * j + 1][1]);
            P[3] = cvt2(s[2 * j + 1][2], s[2 * j + 1][3]);
#pragma unroll
            for (int c = 0; c < 4; c++) {
                uint32_t r0, r1, r2, r3;
                ldm_x4_t(r0, r1, r2, r3,
                         sb + AT_TILE + (uint32_t)((j * 16 + lr) * AT_STRIDE) + c * 32 + lc16);
                uint32_t B0[2] = {r0, r1}, B1[2] = {r2, r3};
                mma16816(O[2 * c],     P, B0);
                mma16816(O[2 * c + 1], P, B1);
            }
        }
        __syncthreads();
    }

    // ---- epilogue: normalize, write fp16 [B,S,D] ----
    const float il0 = 1.f / (l0 > 0.f ? l0 : 1.f);
    const float il1 = 1.f / (l1 > 0.f ? l1 : 1.f);
    const int qr  = q0 + wid * 16 + (lid >> 2);
    const int col0 = h * DKH + (lid & 3) * 2;
#pragma unroll
    for (int nt = 0; nt < 8; nt++) {
        const int col = col0 + nt * 8;
        {
            __half2 p = __floats2half2_rn(O[nt][0] * il0, O[nt][1] * il0);
            *(__half2*)&O_out[((size_t)bz * SEQ + qr) * BDIM + col] = p;
        }
        {
            __half2 p = __floats2half2_rn(O[nt][2] * il1, O[nt][3] * il1);
            *(__half2*)&O_out[((size_t)bz * SEQ + qr + 8) * BDIM + col] = p;
        }
    }
}

// ======================= batched weight transpose (4x D*D, fp32 -> fp16 [N,K]) =======================
__global__ __launch_bounds__(256) void wtrans4_kernel(
    const float* __restrict__ W0, const float* __restrict__ W1_,
    const float* __restrict__ W2_, const float* __restrict__ W3_,
    fp16* __restrict__ T0, fp16* __restrict__ T1,
    fp16* __restrict__ T2, fp16* __restrict__ T3)
{
    __shared__ float t[32][33];
    const int z = blockIdx.z;
    const float* W = (z == 0) ? W0 : (z == 1) ? W1_ : (z == 2) ? W2_ : W3_;
    fp16* T = (z == 0) ? T0 : (z == 1) ? T1 : (z == 2) ? T2 : T3;
    const int n0 = blockIdx.x * 32, k0 = blockIdx.y * 32;
    const int tx = threadIdx.x, ty = threadIdx.y;
#pragma unroll
    for (int j = 0; j < 4; j++)
        t[ty + j * 8][tx] = W[(size_t)(k0 + ty + j * 8) * BDIM + n0 + tx];
    __syncthreads();
#pragma unroll
    for (int j = 0; j < 4; j++)
        T[(size_t)(n0 + ty + j * 8) * BDIM + k0 + tx] = __float2half(t[tx][ty + j * 8]);
}

// ======================= weight transpose (generic) =======================
__global__ __launch_bounds__(256) void wtrans_kernel(
    const float* __restrict__ W, fp16* __restrict__ T16, int K, int N)
{
    __shared__ float t[32][33];
    const int n0 = blockIdx.x * 32, k0 = blockIdx.y * 32;
    const int tx = threadIdx.x, ty = threadIdx.y;
#pragma unroll
    for (int j = 0; j < 4; j++)
        t[ty + j * 8][tx] = W[(size_t)(k0 + ty + j * 8) * N + n0 + tx];
    __syncthreads();
#pragma unroll
    for (int j = 0; j < 4; j++)
        T16[(size_t)(n0 + ty + j * 8) * K + k0 + tx] = __float2half(t[tx][ty + j * 8]);
}

// ======================= fp32 -> fp16 (batched x & y) =======================
__global__ __launch_bounds__(256) void cvt_h2(
    const float* __restrict__ X, fp16* __restrict__ HX,
    const float* __restrict__ Y, fp16* __restrict__ HY)
{
    const float* S = blockIdx.y ? Y : X;
    fp16* Dd = blockIdx.y ? HY : HX;
    const int i = (blockIdx.x * 256 + threadIdx.x) * 4;
    const float4 v = *(const float4*)(S + i);
    *(__half2*)(Dd + i)     = __floats2half2_rn(v.x, v.y);
    *(__half2*)(Dd + i + 2) = __floats2half2_rn(v.z, v.w);
}

// ======================= LayerNorm (+ optional fp16 output) =======================
__global__ __launch_bounds__(256) void ln_kernel(
    const float* __restrict__ X, const float* __restrict__ g,
    const float* __restrict__ b, float* __restrict__ Y, fp16* __restrict__ Yh)
{
    __shared__ float red[2][8];
    __shared__ float stats[2];
    const int row = blockIdx.x;
    const int tid = threadIdx.x;

    const float4 v = ((const float4*)(X + (size_t)row * BDIM))[tid];
    float s = v.x + v.y + v.z + v.w;
    float q = v.x * v.x + v.y * v.y + v.z * v.z + v.w * v.w;
#pragma unroll
    for (int o = 16; o > 0; o >>= 1) {
        s += __shfl_xor_sync(0xffffffffu, s, o);
        q += __shfl_xor_sync(0xffffffffu, q, o);
    }
    const int lane = tid & 31, w = tid >> 5;
    if (lane == 0) { red[0][w] = s; red[1][w] = q; }
    __syncthreads();
    if (tid < 32) {
        s = (tid < 8) ? red[0][tid] : 0.f;
        q = (tid < 8) ? red[1][tid] : 0.f;
#pragma unroll
        for (int o = 4; o > 0; o >>= 1) {
            s += __shfl_xor_sync(0xffffffffu, s, o);
            q += __shfl_xor_sync(0xffffffffu, q, o);
        }
        if (tid == 0) {
            float mean = s * (1.f / BDIM);
            stats[0] = mean;
            stats[1] = rsqrtf(q * (1.f / BDIM) - mean * mean + 1e-5f);
        }
    }
    __syncthreads();
    const float mean = stats[0], rinv = stats[1];
    const float4 gg = ((const float4*)g)[tid];
    const float4 bb = ((const float4*)b)[tid];
    float4 o4;
    o4.x = (v.x - mean) * rinv * gg.x + bb.x;
    o4.y = (v.y - mean) * rinv * gg.y + bb.y;
    o4.z = (v.z - mean) * rinv * gg.z + bb.z;
    o4.w = (v.w - mean) * rinv * gg.w + bb.w;
    if (Y) ((float4*)(Y + (size_t)row * BDIM))[tid] = o4;
    if (Yh) {
        size_t base = (size_t)row * BDIM + tid * 4;
        *(__half2*)(Yh + base)     = __floats2half2_rn(o4.x, o4.y);
        *(__half2*)(Yh + base + 2) = __floats2half2_rn(o4.z, o4.w);
    }
}

// ======================= launcher =======================
extern "C" void kernel_launch(void* const* d_in, const int* in_sizes, int n_in,
                              void* d_out, int out_size)
{
    const float* x    = (const float*)d_in[0];
    const float* y    = (const float*)d_in[1];
    const int*   mask = (const int*)  d_in[2];
    const float* Wq = (const float*)d_in[3];  const float* bq = (const float*)d_in[4];
    const float* Wk = (const float*)d_in[5];  const float* bk = (const float*)d_in[6];
    const float* Wv = (const float*)d_in[7];  const float* bv = (const float*)d_in[8];
    const float* Wo = (const float*)d_in[9];  const float* bo = (const float*)d_in[10];
    const float* W1 = (const float*)d_in[11]; const float* b1 = (const float*)d_in[12];
    const float* W2 = (const float*)d_in[13]; const float* b2 = (const float*)d_in[14];
    const float* g1 = (const float*)d_in[15]; const float* be1 = (const float*)d_in[16];
    const float* g2 = (const float*)d_in[17]; const float* be2 = (const float*)d_in[18];
    float* out = (float*)d_out;

    float *s1p, *x1p, *s2p;
    fp16 *xh, *yh, *qh, *kh, *vh, *ah, *x1h, *hh;
    fp16 *wq, *wk, *wv, *wo, *w1, *w2;
    cudaGetSymbolAddress((void**)&s1p, g_s1);  cudaGetSymbolAddress((void**)&x1p, g_x1);
    cudaGetSymbolAddress((void**)&s2p, g_s2);
    cudaGetSymbolAddress((void**)&xh, g_xh);   cudaGetSymbolAddress((void**)&yh, g_yh);
    cudaGetSymbolAddress((void**)&qh, g_Qh);   cudaGetSymbolAddress((void**)&kh, g_Kh);
    cudaGetSymbolAddress((void**)&vh, g_Vh);   cudaGetSymbolAddress((void**)&ah, g_ah);
    cudaGetSymbolAddress((void**)&x1h, g_x1h); cudaGetSymbolAddress((void**)&hh, g_hh);
    cudaGetSymbolAddress((void**)&wq, g_wqT);  cudaGetSymbolAddress((void**)&wk, g_wkT);
    cudaGetSymbolAddress((void**)&wv, g_wvT);  cudaGetSymbolAddress((void**)&wo, g_woT);
    cudaGetSymbolAddress((void**)&w1, g_w1T);  cudaGetSymbolAddress((void**)&w2, g_w2T);

    cudaFuncSetAttribute(mma_gemm, cudaFuncAttributeMaxDynamicSharedMemorySize, GEMM_SMEM);
    cudaFuncSetAttribute(attn_tc,  cudaFuncAttributeMaxDynamicSharedMemorySize, AT_SMEM);

    // ---- weight prep: 4 D*D transposes in one launch + 2 big ones ----
    dim3 tb(32, 8);
    wtrans4_kernel<<<dim3(BDIM / 32, BDIM / 32, 4), tb>>>(Wq, Wk, Wv, Wo, wq, wk, wv, wo);
    wtrans_kernel<<<dim3(HIDN / 32, BDIM / 32), tb>>>(W1, w1, BDIM, HIDN);
    wtrans_kernel<<<dim3(BDIM / 32, HIDN / 32), tb>>>(W2, w2, HIDN, BDIM);

    // ---- activation fp16 conversion (x and y in one launch) ----
    cvt_h2<<<dim3((MROWS * BDIM) / 1024, 2), 256>>>(x, xh, y, yh);

    dim3 gD(BDIM / 128, MROWS / 128);
    dim3 gH(HIDN / 128, MROWS / 128);

    // QKV projections -> [B,H,S,DK] fp16
    mma_gemm<<<gD, 128, GEMM_SMEM>>>(xh, wq, bq, nullptr, nullptr, qh, MROWS, BDIM, BDIM, MODE_SPLIT_H);
    mma_gemm<<<gD, 128, GEMM_SMEM>>>(yh, wk, bk, nullptr, nullptr, kh, MROWS, BDIM, BDIM, MODE_SPLIT_H);
    mma_gemm<<<gD, 128, GEMM_SMEM>>>(yh, wv, bv, nullptr, nullptr, vh, MROWS, BDIM, BDIM, MODE_SPLIT_H);

    // tensor-core flash attention -> fp16 [B,S,D]
    attn_tc<<<dim3(SEQ / 128, NH, NB), 256, AT_SMEM>>>(qh, kh, vh, mask, ah);

    // s1 = x + attn @ Wo + bo ; x1 = LN(s1) (+fp16)
    mma_gemm<<<gD, 128, GEMM_SMEM>>>(ah, wo, bo, x, s1p, nullptr, MROWS, BDIM, BDIM, MODE_RES);
    ln_kernel<<<MROWS, 256>>>(s1p, g1, be1, x1p, x1h);

    // FFN
    mma_gemm<<<gH, 128, GEMM_SMEM>>>(x1h, w1, b1, nullptr, nullptr, hh, MROWS, HIDN, BDIM, MODE_RELU_H);
    mma_gemm<<<gD, 128, GEMM_SMEM>>>(hh, w2, b2, x1p, s2p, nullptr, MROWS, BDIM, HIDN, MODE_RES);
    ln_kernel<<<MROWS, 256>>>(s2p, g2, be2, out, nullptr);
}

// round 12
// speedup vs baseline: 1.0191x; 1.0191x over previous
#include <cuda_runtime.h>
#include <cuda_fp16.h>
#include <math.h>
#include <stdint.h>

#define BDIM 1024
#define SEQ  2048
#define NH   16
#define DKH  64
#define HIDN 4096
#define MROWS 4096   // B*S
#define NB   2

typedef __half fp16;

// ---------------- scratch (static device globals; no allocation) ----------------
__device__ float g_s1 [MROWS * BDIM];
__device__ float g_x1 [MROWS * BDIM];
__device__ float g_s2 [MROWS * BDIM];

__device__ fp16 g_xh  [MROWS * BDIM];
__device__ fp16 g_yh  [MROWS * BDIM];
__device__ fp16 g_Qh  [MROWS * BDIM];   // [B,H,S,DK]
__device__ fp16 g_Kh  [MROWS * BDIM];
__device__ fp16 g_Vh  [MROWS * BDIM];
__device__ fp16 g_ah  [MROWS * BDIM];   // attention output [B,S,D]
__device__ fp16 g_x1h [MROWS * BDIM];
__device__ fp16 g_hh  [MROWS * HIDN];

// transposed weights: Wt[N][K] fp16
__device__ fp16 g_wqT [BDIM * BDIM];
__device__ fp16 g_wkvT[2 * BDIM * BDIM];   // [Wk^T ; Wv^T]
__device__ fp16 g_woT [BDIM * BDIM];
__device__ fp16 g_w1T [HIDN * BDIM];
__device__ fp16 g_w2T [BDIM * HIDN];

enum { MODE_RELU_H = 1, MODE_RES = 2, MODE_SPLIT_H = 4 };

// ======================= PTX helpers =======================
__device__ __forceinline__ uint32_t smem_u32(const void* p) {
    uint32_t a;
    asm("{ .reg .u64 t; cvta.to.shared.u64 t, %1; cvt.u32.u64 %0, t; }" : "=r"(a) : "l"(p));
    return a;
}
__device__ __forceinline__ void cp16(uint32_t s, const void* g) {
    asm volatile("cp.async.cg.shared.global [%0], [%1], 16;" :: "r"(s), "l"(g));
}
#define CP_COMMIT() asm volatile("cp.async.commit_group;" ::: "memory")
#define CP_WAIT0()  asm volatile("cp.async.wait_group 0;" ::: "memory")
#define CP_WAIT1()  asm volatile("cp.async.wait_group 1;" ::: "memory")
#define CP_WAIT2()  asm volatile("cp.async.wait_group 2;" ::: "memory")

__device__ __forceinline__ void ldm_x4(uint32_t& r0, uint32_t& r1, uint32_t& r2, uint32_t& r3, uint32_t a) {
    asm volatile("ldmatrix.sync.aligned.m8n8.x4.shared.b16 {%0,%1,%2,%3}, [%4];"
                 : "=r"(r0), "=r"(r1), "=r"(r2), "=r"(r3) : "r"(a));
}
__device__ __forceinline__ void ldm_x4_t(uint32_t& r0, uint32_t& r1, uint32_t& r2, uint32_t& r3, uint32_t a) {
    asm volatile("ldmatrix.sync.aligned.m8n8.x4.trans.shared.b16 {%0,%1,%2,%3}, [%4];"
                 : "=r"(r0), "=r"(r1), "=r"(r2), "=r"(r3) : "r"(a));
}
__device__ __forceinline__ void mma16816(float* c, const uint32_t* a, const uint32_t* b) {
    asm volatile("mma.sync.aligned.m16n8k16.row.col.f32.f16.f16.f32 "
                 "{%0,%1,%2,%3}, {%4,%5,%6,%7}, {%8,%9}, {%0,%1,%2,%3};"
                 : "+f"(c[0]), "+f"(c[1]), "+f"(c[2]), "+f"(c[3])
                 : "r"(a[0]), "r"(a[1]), "r"(a[2]), "r"(a[3]), "r"(b[0]), "r"(b[1]));
}
__device__ __forceinline__ uint32_t cvt2(float a, float b) {
    __half2 t = __floats2half2_rn(a, b);
    return *(uint32_t*)&t;
}

// ======================= mma.sync fp16 GEMM (R10 shape: 8 warps, 64x32 warp tile) =======================
// C[M,N] = A[M,K] @ Wt[N,K]^T, fp32 accum.
// CTA 128x128, BK=32, 256 threads = 8 warps (2 M x 4 N), 3-stage cp.async pipeline.
// MODE_SPLIT_H supports fused dual-output: columns [0,BDIM) -> outH (biasA),
// columns [BDIM,2*BDIM) -> outH2 (biasB). Single-output GEMMs pass outH2=null.
#define BK 32
#define APAD 40
#define TILE_B (128 * APAD * 2)        // 10240 B
#define SLAB_B (2 * TILE_B)            // A, B
#define GEMM_SMEM (3 * SLAB_B)         // 61440 B (3 stages)

__global__ __launch_bounds__(256, 2) void mma_gemm(
    const fp16* __restrict__ A, const fp16* __restrict__ B,
    const float* __restrict__ biasA, const float* __restrict__ biasB,
    const float* __restrict__ R,
    float* __restrict__ outF, fp16* __restrict__ outH, fp16* __restrict__ outH2,
    int M, int N, int K, int mode)
{
    extern __shared__ char sm[];
    const uint32_t smb = smem_u32(sm);
    const int tid = threadIdx.x;
    const int wid = tid >> 5;
    const int lid = tid & 31;
    const int warp_m = wid >> 2;
    const int warp_n = wid & 3;
    const int row0 = blockIdx.y * 128;
    const int col0 = blockIdx.x * 128;

    const fp16* src[2];
    src[0] = A + (size_t)row0 * K;
    src[1] = B + (size_t)col0 * K;

    const int NS = K / BK;

#define LOAD_SLAB(ST, KS) do {                                                \
        const uint32_t _sb = smb + (ST) * SLAB_B;                             \
        const int _ko = (KS) * BK;                                            \
        _Pragma("unroll")                                                     \
        for (int t = 0; t < 2; t++) {                                         \
            const fp16* g = src[t] + _ko;                                     \
            const uint32_t tb = _sb + t * TILE_B;                             \
            _Pragma("unroll")                                                 \
            for (int u = 0; u < 2; u++) {                                     \
                int p = tid + u * 256;                                        \
                int r = p >> 2, c = p & 3;                                    \
                cp16(tb + (uint32_t)(r * (APAD * 2) + c * 16),                \
                     g + (size_t)r * K + c * 8);                              \
            }                                                                 \
        }                                                                     \
        CP_COMMIT();                                                          \
    } while (0)

    float acc[4][4][4];
#pragma unroll
    for (int i = 0; i < 4; i++)
#pragma unroll
        for (int j = 0; j < 4; j++)
#pragma unroll
            for (int f = 0; f < 4; f++) acc[i][j][f] = 0.f;

    LOAD_SLAB(0, 0);
    LOAD_SLAB(1, 1);   // K >= 1024 always => NS >= 32

    const uint32_t lrow = (uint32_t)(lid & 15);
    const uint32_t lcol16 = (uint32_t)(lid >> 4) * 16;

    int st = 0;
    for (int s = 0; s < NS; s++) {
        if (s + 2 < NS) { LOAD_SLAB((st + 2) % 3, s + 2); CP_WAIT2(); }
        else if (s + 1 < NS) { CP_WAIT1(); }
        else { CP_WAIT0(); }
        __syncthreads();

        const uint32_t ab = smb + st * SLAB_B;
        const uint32_t bb = ab + TILE_B;

#pragma unroll
        for (int kk = 0; kk < 2; kk++) {
            const uint32_t koff = kk * 32 + lcol16;

            uint32_t af[4][4];
#pragma unroll
            for (int mi = 0; mi < 4; mi++) {
                uint32_t ra = (uint32_t)((warp_m * 64 + mi * 16 + lrow) * (APAD * 2)) + koff;
                ldm_x4(af[mi][0], af[mi][1], af[mi][2], af[mi][3], ab + ra);
            }
            uint32_t bf[4][2];
#pragma unroll
            for (int nt = 0; nt < 2; nt++) {
                uint32_t rb = (uint32_t)((warp_n * 32 + nt * 16 + lrow) * (APAD * 2)) + koff;
                uint32_t r0, r1, r2, r3;
                ldm_x4(r0, r1, r2, r3, bb + rb);
                bf[nt * 2 + 0][0] = r0; bf[nt * 2 + 0][1] = r2;
                bf[nt * 2 + 1][0] = r1; bf[nt * 2 + 1][1] = r3;
            }
#pragma unroll
            for (int mi = 0; mi < 4; mi++)
#pragma unroll
                for (int ni = 0; ni < 4; ni++)
                    mma16816(acc[mi][ni], af[mi], bf[ni]);
        }
        __syncthreads();
        st = (st + 1) % 3;
    }

    // ---- epilogue ----
    const int qr = lid >> 2;
    const int qc = (lid & 3) * 2;
#pragma unroll
    for (int mi = 0; mi < 4; mi++) {
#pragma unroll
        for (int ni = 0; ni < 4; ni++) {
            const int n = col0 + warp_n * 32 + ni * 8 + qc;
            // dual-output column routing (only meaningful for MODE_SPLIT_H fused KV)
            const bool second = (n >= BDIM) && (outH2 != nullptr);
            const int nn = second ? (n - BDIM) : n;
            const float* bp = second ? biasB : biasA;
            const float b0 = bp[nn], b1 = bp[nn + 1];
            fp16* dst = second ? outH2 : outH;
#pragma unroll
            for (int half = 0; half < 2; half++) {
                const int m = row0 + warp_m * 64 + mi * 16 + qr + half * 8;
                float v0 = acc[mi][ni][half * 2 + 0] + b0;
                float v1 = acc[mi][ni][half * 2 + 1] + b1;
                if (mode == MODE_RES) {
                    const float* rp = &R[(size_t)m * N + n];
                    v0 += rp[0]; v1 += rp[1];
                    float2 o2 = {v0, v1};
                    *(float2*)&outF[(size_t)m * N + n] = o2;
                } else if (mode == MODE_SPLIT_H) {
                    int hh = nn >> 6, dk = nn & 63, bb = m >> 11, ss = m & 2047;
                    size_t o = (((size_t)(bb * NH + hh)) * SEQ + ss) * DKH + dk;
                    *(__half2*)&dst[o] = __floats2half2_rn(v0, v1);
                } else { // MODE_RELU_H
                    v0 = fmaxf(v0, 0.f); v1 = fmaxf(v1, 0.f);
                    *(__half2*)&outH[(size_t)m * N + n] = __floats2half2_rn(v0, v1);
                }
            }
        }
    }
}

// ======================= tensor-core flash attention (fp16, single-pass) =======================
#define AT_STRIDE 144
#define AT_TILE   (64 * AT_STRIDE)            // 9216 B per 64x64 fp16 tile
#define AT_STAGE  (2 * AT_TILE)               // K, V
#define AT_MSK    (2 * AT_STAGE)              // 36864
#define AT_SMEM   (AT_MSK + 512)

__global__ __launch_bounds__(256, 2) void attn_tc(
    const fp16* __restrict__ Qg, const fp16* __restrict__ Kg,
    const fp16* __restrict__ Vg, const int* __restrict__ mask,
    fp16* __restrict__ O_out)
{
    extern __shared__ char sm[];
    const uint32_t smb = smem_u32(sm);
    const int tid = threadIdx.x;
    const int wid = tid >> 5;
    const int lid = tid & 31;
    const int q0  = blockIdx.x * 128;
    const int h   = blockIdx.y;
    const int bz  = blockIdx.z;
    const size_t hoff = ((size_t)(bz * NH + h)) * SEQ * DKH;

    const uint32_t lr   = (uint32_t)(lid & 15);
    const uint32_t lc16 = (uint32_t)(lid >> 4) * 16;

    // ---- Q tile -> smem, then register fragments ----
    {
        const fp16* qh = Qg + hoff + (size_t)q0 * DKH;
#pragma unroll
        for (int u = 0; u < 4; u++) {
            int p = tid + u * 256;
            int r = p >> 3, c = p & 7;
            cp16(smb + (uint32_t)(r * AT_STRIDE + c * 16), qh + (size_t)r * DKH + c * 8);
        }
        CP_COMMIT(); CP_WAIT0();
    }
    __syncthreads();
    uint32_t qf[4][4];
#pragma unroll
    for (int ks = 0; ks < 4; ks++) {
        uint32_t ra = (uint32_t)((wid * 16 + lr) * AT_STRIDE) + ks * 32 + lc16;
        ldm_x4(qf[ks][0], qf[ks][1], qf[ks][2], qf[ks][3], smb + ra);
    }
    __syncthreads();

    float O[8][4];
#pragma unroll
    for (int i = 0; i < 8; i++)
#pragma unroll
        for (int j = 0; j < 4; j++) O[i][j] = 0.f;
    float m0 = -INFINITY, m1 = -INFINITY, l0 = 0.f, l1 = 0.f;

    const fp16* kg = Kg + hoff;
    const fp16* vg = Vg + hoff;
    const int*  mkg = mask + bz * SEQ;

#define LOAD_KV(ST, T) do {                                                     \
        const uint32_t _sb = smb + (ST) * AT_STAGE;                             \
        const int _k0 = (T) * 64;                                               \
        _Pragma("unroll")                                                       \
        for (int u = 0; u < 2; u++) {                                           \
            int p = tid + u * 256;                                              \
            int r = p >> 3, c = p & 7;                                          \
            uint32_t so = (uint32_t)(r * AT_STRIDE + c * 16);                   \
            size_t go = (size_t)(_k0 + r) * DKH + c * 8;                        \
            cp16(_sb + so, kg + go);                                            \
            cp16(_sb + AT_TILE + so, vg + go);                                  \
        }                                                                       \
        if (tid < 16) cp16(smb + AT_MSK + (ST) * 256 + tid * 16, mkg + _k0 + tid * 4); \
        CP_COMMIT();                                                            \
    } while (0)

    LOAD_KV(0, 0);

    for (int t = 0; t < SEQ / 64; t++) {
        const int st = t & 1;
        if (t + 1 < SEQ / 64) { LOAD_KV(st ^ 1, t + 1); CP_WAIT1(); }
        else                  { CP_WAIT0(); }
        __syncthreads();

        const uint32_t sb = smb + st * AT_STAGE;
        const int* msk = (const int*)(sm + AT_MSK + st * 256);

        // ---- scores: single-pass QK^T ----
        float s[8][4];
#pragma unroll
        for (int i = 0; i < 8; i++)
#pragma unroll
            for (int j = 0; j < 4; j++) s[i][j] = 0.f;

#pragma unroll
        for (int ks = 0; ks < 4; ks++) {
            const uint32_t koff = ks * 32 + lc16;
#pragma unroll
            for (int g = 0; g < 4; g++) {
                uint32_t rb = (uint32_t)((g * 16 + lr) * AT_STRIDE) + koff;
                uint32_t r0, r1, r2, r3;
                ldm_x4(r0, r1, r2, r3, sb + rb);
                uint32_t b0[2] = {r0, r2}, b1[2] = {r1, r3};
                mma16816(s[2 * g],     qf[ks], b0);
                mma16816(s[2 * g + 1], qf[ks], b1);
            }
        }

        // ---- mask + scale ----
#pragma unroll
        for (int j = 0; j < 8; j++) {
            int c0 = j * 8 + (lid & 3) * 2;
            bool z0 = (msk[c0] == 0), z1 = (msk[c0 + 1] == 0);
            s[j][0] = z0 ? -1e9f : s[j][0] * 0.125f;
            s[j][2] = z0 ? -1e9f : s[j][2] * 0.125f;
            s[j][1] = z1 ? -1e9f : s[j][1] * 0.125f;
            s[j][3] = z1 ? -1e9f : s[j][3] * 0.125f;
        }

        // ---- online softmax (rows r and r+8) ----
        float mx0 = -INFINITY, mx1 = -INFINITY;
#pragma unroll
        for (int j = 0; j < 8; j++) {
            mx0 = fmaxf(mx0, fmaxf(s[j][0], s[j][1]));
            mx1 = fmaxf(mx1, fmaxf(s[j][2], s[j][3]));
        }
#pragma unroll
        for (int off = 1; off <= 2; off <<= 1) {
            mx0 = fmaxf(mx0, __shfl_xor_sync(0xffffffffu, mx0, off));
            mx1 = fmaxf(mx1, __shfl_xor_sync(0xffffffffu, mx1, off));
        }
        float nm0 = fmaxf(m0, mx0), nm1 = fmaxf(m1, mx1);
        float a0 = __expf(m0 - nm0), a1 = __expf(m1 - nm1);
        float sum0 = 0.f, sum1 = 0.f;
#pragma unroll
        for (int j = 0; j < 8; j++) {
            s[j][0] = __expf(s[j][0] - nm0); sum0 += s[j][0];
            s[j][1] = __expf(s[j][1] - nm0); sum0 += s[j][1];
            s[j][2] = __expf(s[j][2] - nm1); sum1 += s[j][2];
            s[j][3] = __expf(s[j][3] - nm1); sum1 += s[j][3];
        }
#pragma unroll
        for (int off = 1; off <= 2; off <<= 1) {
            sum0 += __shfl_xor_sync(0xffffffffu, sum0, off);
            sum1 += __shfl_xor_sync(0xffffffffu, sum1, off);
        }
        l0 = l0 * a0 + sum0;
        l1 = l1 * a1 + sum1;
        m0 = nm0; m1 = nm1;
#pragma unroll
        for (int i = 0; i < 8; i++) {
            O[i][0] *= a0; O[i][1] *= a0;
            O[i][2] *= a1; O[i][3] *= a1;
        }

        // ---- O += P @ V (P from registers, V via ldmatrix.trans) ----
#pragma unroll
        for (int j = 0; j < 4; j++) {
            uint32_t P[4];
            P[0] = cvt2(s[2 * j][0],     s[2 * j][1]);
            P[1] = cvt2(s[2 * j][2],     s[2 * j][3]);
            P[2] = cvt2(s[2 * j + 1][0], s[2 * j + 1][1]);
            P[3] = cvt2(s[2 * j + 1][2], s[2 * j + 1][3]);
#pragma unroll
            for (int c = 0; c < 4; c++) {
                uint32_t r0, r1, r2, r3;
                ldm_x4_t(r0, r1, r2, r3,
                         sb + AT_TILE + (uint32_t)((j * 16 + lr) * AT_STRIDE) + c * 32 + lc16);
                uint32_t B0[2] = {r0, r1}, B1[2] = {r2, r3};
                mma16816(O[2 * c],     P, B0);
                mma16816(O[2 * c + 1], P, B1);
            }
        }
        __syncthreads();
    }

    // ---- epilogue: normalize, write fp16 [B,S,D] ----
    const float il0 = 1.f / (l0 > 0.f ? l0 : 1.f);
    const float il1 = 1.f / (l1 > 0.f ? l1 : 1.f);
    const int qr  = q0 + wid * 16 + (lid >> 2);
    const int col0 = h * DKH + (lid & 3) * 2;
#pragma unroll
    for (int nt = 0; nt < 8; nt++) {
        const int col = col0 + nt * 8;
        {
            __half2 p = __floats2half2_rn(O[nt][0] * il0, O[nt][1] * il0);
            *(__half2*)&O_out[((size_t)bz * SEQ + qr) * BDIM + col] = p;
        }
        {
            __half2 p = __floats2half2_rn(O[nt][2] * il1, O[nt][3] * il1);
            *(__half2*)&O_out[((size_t)bz * SEQ + qr + 8) * BDIM + col] = p;
        }
    }
}

// ======================= batched weight transpose (4x D*D, fp32 -> fp16 [N,K]) =======================
__global__ __launch_bounds__(256) void wtrans4_kernel(
    const float* __restrict__ W0, const float* __restrict__ W1_,
    const float* __restrict__ W2_, const float* __restrict__ W3_,
    fp16* __restrict__ T0, fp16* __restrict__ T1,
    fp16* __restrict__ T2, fp16* __restrict__ T3)
{
    __shared__ float t[32][33];
    const int z = blockIdx.z;
    const float* W = (z == 0) ? W0 : (z == 1) ? W1_ : (z == 2) ? W2_ : W3_;
    fp16* T = (z == 0) ? T0 : (z == 1) ? T1 : (z == 2) ? T2 : T3;
    const int n0 = blockIdx.x * 32, k0 = blockIdx.y * 32;
    const int tx = threadIdx.x, ty = threadIdx.y;
#pragma unroll
    for (int j = 0; j < 4; j++)
        t[ty + j * 8][tx] = W[(size_t)(k0 + ty + j * 8) * BDIM + n0 + tx];
    __syncthreads();
#pragma unroll
    for (int j = 0; j < 4; j++)
        T[(size_t)(n0 + ty + j * 8) * BDIM + k0 + tx] = __float2half(t[tx][ty + j * 8]);
}

// ======================= weight transpose (generic) =======================
__global__ __launch_bounds__(256) void wtrans_kernel(
    const float* __restrict__ W, fp16* __restrict__ T16, int K, int N)
{
    __shared__ float t[32][33];
    const int n0 = blockIdx.x * 32, k0 = blockIdx.y * 32;
    const int tx = threadIdx.x, ty = threadIdx.y;
#pragma unroll
    for (int j = 0; j < 4; j++)
        t[ty + j * 8][tx] = W[(size_t)(k0 + ty + j * 8) * N + n0 + tx];
    __syncthreads();
#pragma unroll
    for (int j = 0; j < 4; j++)
        T16[(size_t)(n0 + ty + j * 8) * K + k0 + tx] = __float2half(t[tx][ty + j * 8]);
}

// ======================= fp32 -> fp16 (batched x & y) =======================
__global__ __launch_bounds__(256) void cvt_h2(
    const float* __restrict__ X, fp16* __restrict__ HX,
    const float* __restrict__ Y, fp16* __restrict__ HY)
{
    const float* S = blockIdx.y ? Y : X;
    fp16* Dd = blockIdx.y ? HY : HX;
    const int i = (blockIdx.x * 256 + threadIdx.x) * 4;
    const float4 v = *(const float4*)(S + i);
    *(__half2*)(Dd + i)     = __floats2half2_rn(v.x, v.y);
    *(__half2*)(Dd + i + 2) = __floats2half2_rn(v.z, v.w);
}

// ======================= LayerNorm (+ optional fp16 output) =======================
__global__ __launch_bounds__(256) void ln_kernel(
    const float* __restrict__ X, const float* __restrict__ g,
    const float* __restrict__ b, float* __restrict__ Y, fp16* __restrict__ Yh)
{
    __shared__ float red[2][8];
    __shared__ float stats[2];
    const int row = blockIdx.x;
    const int tid = threadIdx.x;

    const float4 v = ((const float4*)(X + (size_t)row * BDIM))[tid];
    float s = v.x + v.y + v.z + v.w;
    float q = v.x * v.x + v.y * v.y + v.z * v.z + v.w * v.w;
#pragma unroll
    for (int o = 16; o > 0; o >>= 1) {
        s += __shfl_xor_sync(0xffffffffu, s, o);
        q += __shfl_xor_sync(0xffffffffu, q, o);
    }
    const int lane = tid & 31, w = tid >> 5;
    if (lane == 0) { red[0][w] = s; red[1][w] = q; }
    __syncthreads();
    if (tid < 32) {
        s = (tid < 8) ? red[0][tid] : 0.f;
        q = (tid < 8) ? red[1][tid] : 0.f;
#pragma unroll
        for (int o = 4; o > 0; o >>= 1) {
            s += __shfl_xor_sync(0xffffffffu, s, o);
            q += __shfl_xor_sync(0xffffffffu, q, o);
        }
        if (tid == 0) {
            float mean = s * (1.f / BDIM);
            stats[0] = mean;
            stats[1] = rsqrtf(q * (1.f / BDIM) - mean * mean + 1e-5f);
        }
    }
    __syncthreads();
    const float mean = stats[0], rinv = stats[1];
    const float4 gg = ((const float4*)g)[tid];
    const float4 bb = ((const float4*)b)[tid];
    float4 o4;
    o4.x = (v.x - mean) * rinv * gg.x + bb.x;
    o4.y = (v.y - mean) * rinv * gg.y + bb.y;
    o4.z = (v.z - mean) * rinv * gg.z + bb.z;
    o4.w = (v.w - mean) * rinv * gg.w + bb.w;
    if (Y) ((float4*)(Y + (size_t)row * BDIM))[tid] = o4;
    if (Yh) {
        size_t base = (size_t)row * BDIM + tid * 4;
        *(__half2*)(Yh + base)     = __floats2half2_rn(o4.x, o4.y);
        *(__half2*)(Yh + base + 2) = __floats2half2_rn(o4.z, o4.w);
    }
}

// ======================= launcher =======================
extern "C" void kernel_launch(void* const* d_in, const int* in_sizes, int n_in,
                              void* d_out, int out_size)
{
    const float* x    = (const float*)d_in[0];
    const float* y    = (const float*)d_in[1];
    const int*   mask = (const int*)  d_in[2];
    const float* Wq = (const float*)d_in[3];  const float* bq = (const float*)d_in[4];
    const float* Wk = (const float*)d_in[5];  const float* bk = (const float*)d_in[6];
    const float* Wv = (const float*)d_in[7];  const float* bv = (const float*)d_in[8];
    const float* Wo = (const float*)d_in[9];  const float* bo = (const float*)d_in[10];
    const float* W1 = (const float*)d_in[11]; const float* b1 = (const float*)d_in[12];
    const float* W2 = (const float*)d_in[13]; const float* b2 = (const float*)d_in[14];
    const float* g1 = (const float*)d_in[15]; const float* be1 = (const float*)d_in[16];
    const float* g2 = (const float*)d_in[17]; const float* be2 = (const float*)d_in[18];
    float* out = (float*)d_out;

    float *s1p, *x1p, *s2p;
    fp16 *xh, *yh, *qh, *kh, *vh, *ah, *x1h, *hh;
    fp16 *wq, *wkv, *wo, *w1, *w2;
    cudaGetSymbolAddress((void**)&s1p, g_s1);  cudaGetSymbolAddress((void**)&x1p, g_x1);
    cudaGetSymbolAddress((void**)&s2p, g_s2);
    cudaGetSymbolAddress((void**)&xh, g_xh);   cudaGetSymbolAddress((void**)&yh, g_yh);
    cudaGetSymbolAddress((void**)&qh, g_Qh);   cudaGetSymbolAddress((void**)&kh, g_Kh);
    cudaGetSymbolAddress((void**)&vh, g_Vh);   cudaGetSymbolAddress((void**)&ah, g_ah);
    cudaGetSymbolAddress((void**)&x1h, g_x1h); cudaGetSymbolAddress((void**)&hh, g_hh);
    cudaGetSymbolAddress((void**)&wq, g_wqT);  cudaGetSymbolAddress((void**)&wkv, g_wkvT);
    cudaGetSymbolAddress((void**)&wo, g_woT);
    cudaGetSymbolAddress((void**)&w1, g_w1T);  cudaGetSymbolAddress((void**)&w2, g_w2T);

    cudaFuncSetAttribute(mma_gemm, cudaFuncAttributeMaxDynamicSharedMemorySize, GEMM_SMEM);
    cudaFuncSetAttribute(attn_tc,  cudaFuncAttributeMaxDynamicSharedMemorySize, AT_SMEM);

    // ---- weight prep: Wq, Wk->wkv[0:D*D], Wv->wkv[D*D:], Wo in one launch + 2 big ones ----
    dim3 tb(32, 8);
    wtrans4_kernel<<<dim3(BDIM / 32, BDIM / 32, 4), tb>>>(
        Wq, Wk, Wv, Wo, wq, wkv, wkv + (size_t)BDIM * BDIM, wo);
    wtrans_kernel<<<dim3(HIDN / 32, BDIM / 32), tb>>>(W1, w1, BDIM, HIDN);
    wtrans_kernel<<<dim3(BDIM / 32, HIDN / 32), tb>>>(W2, w2, HIDN, BDIM);

    // ---- activation fp16 conversion (x and y in one launch) ----
    cvt_h2<<<dim3((MROWS * BDIM) / 1024, 2), 256>>>(x, xh, y, yh);

    dim3 gD(BDIM / 128, MROWS / 128);          // 8 x 32 = 256 CTAs
    dim3 gKV(2 * BDIM / 128, MROWS / 128);     // 16 x 32 = 512 CTAs (fused K+V)
    dim3 gH(HIDN / 128, MROWS / 128);          // 32 x 32

    // Q projection -> [B,H,S,DK] fp16
    mma_gemm<<<gD, 256, GEMM_SMEM>>>(xh, wq, bq, nullptr, nullptr,
                                     nullptr, qh, nullptr, MROWS, BDIM, BDIM, MODE_SPLIT_H);
    // fused K+V projection -> kh, vh
    mma_gemm<<<gKV, 256, GEMM_SMEM>>>(yh, wkv, bk, bv, nullptr,
                                      nullptr, kh, vh, MROWS, 2 * BDIM, BDIM, MODE_SPLIT_H);

    // tensor-core flash attention -> fp16 [B,S,D]
    attn_tc<<<dim3(SEQ / 128, NH, NB), 256, AT_SMEM>>>(qh, kh, vh, mask, ah);

    // s1 = x + attn @ Wo + bo ; x1 = LN(s1) (+fp16)
    mma_gemm<<<gD, 256, GEMM_SMEM>>>(ah, wo, bo, nullptr, x,
                                     s1p, nullptr, nullptr, MROWS, BDIM, BDIM, MODE_RES);
    ln_kernel<<<MROWS, 256>>>(s1p, g1, be1, x1p, x1h);

    // FFN
    mma_gemm<<<gH, 256, GEMM_SMEM>>>(x1h, w1, b1, nullptr, nullptr,
                                     nullptr, hh, nullptr, MROWS, HIDN, BDIM, MODE_RELU_H);
    mma_gemm<<<gD, 256, GEMM_SMEM>>>(hh, w2, b2, nullptr, x1p,
                                     s2p, nullptr, nullptr, MROWS, BDIM, HIDN, MODE_RES);
    ln_kernel<<<MROWS, 256>>>(s2p, g2, be2, out, nullptr);
}

// round 13
// speedup vs baseline: 1.1226x; 1.1016x over previous
#include <cuda_runtime.h>
#include <cuda_fp16.h>
#include <math.h>
#include <stdint.h>

#define BDIM 1024
#define SEQ  2048
#define NH   16
#define DKH  64
#define HIDN 4096
#define MROWS 4096   // B*S
#define NB   2

typedef __half fp16;

// ---------------- scratch (static device globals; no allocation) ----------------
__device__ float g_s1 [MROWS * BDIM];
__device__ float g_x1 [MROWS * BDIM];
__device__ float g_s2 [MROWS * BDIM];

__device__ fp16 g_xh  [MROWS * BDIM];
__device__ fp16 g_yh  [MROWS * BDIM];
__device__ fp16 g_Qh  [MROWS * BDIM];   // [B,H,S,DK]
__device__ fp16 g_Kh  [MROWS * BDIM];
__device__ fp16 g_Vh  [MROWS * BDIM];
__device__ fp16 g_ah  [MROWS * BDIM];   // attention output [B,S,D]
__device__ fp16 g_x1h [MROWS * BDIM];
__device__ fp16 g_hh  [MROWS * HIDN];

// transposed weights: Wt[N][K] fp16
__device__ fp16 g_wqT [BDIM * BDIM];
__device__ fp16 g_wkvT[2 * BDIM * BDIM];   // [Wk^T ; Wv^T]
__device__ fp16 g_woT [BDIM * BDIM];
__device__ fp16 g_w1T [HIDN * BDIM];
__device__ fp16 g_w2T [BDIM * HIDN];

enum { MODE_RELU_H = 1, MODE_RES = 2, MODE_SPLIT_H = 4 };

// ======================= PTX helpers =======================
__device__ __forceinline__ uint32_t smem_u32(const void* p) {
    uint32_t a;
    asm("{ .reg .u64 t; cvta.to.shared.u64 t, %1; cvt.u32.u64 %0, t; }" : "=r"(a) : "l"(p));
    return a;
}
__device__ __forceinline__ void cp16(uint32_t s, const void* g) {
    asm volatile("cp.async.cg.shared.global [%0], [%1], 16;" :: "r"(s), "l"(g));
}
#define CP_COMMIT() asm volatile("cp.async.commit_group;" ::: "memory")
#define CP_WAIT0()  asm volatile("cp.async.wait_group 0;" ::: "memory")
#define CP_WAIT1()  asm volatile("cp.async.wait_group 1;" ::: "memory")

__device__ __forceinline__ void ldm_x4(uint32_t& r0, uint32_t& r1, uint32_t& r2, uint32_t& r3, uint32_t a) {
    asm volatile("ldmatrix.sync.aligned.m8n8.x4.shared.b16 {%0,%1,%2,%3}, [%4];"
                 : "=r"(r0), "=r"(r1), "=r"(r2), "=r"(r3) : "r"(a));
}
__device__ __forceinline__ void ldm_x4_t(uint32_t& r0, uint32_t& r1, uint32_t& r2, uint32_t& r3, uint32_t a) {
    asm volatile("ldmatrix.sync.aligned.m8n8.x4.trans.shared.b16 {%0,%1,%2,%3}, [%4];"
                 : "=r"(r0), "=r"(r1), "=r"(r2), "=r"(r3) : "r"(a));
}
__device__ __forceinline__ void mma16816(float* c, const uint32_t* a, const uint32_t* b) {
    asm volatile("mma.sync.aligned.m16n8k16.row.col.f32.f16.f16.f32 "
                 "{%0,%1,%2,%3}, {%4,%5,%6,%7}, {%8,%9}, {%0,%1,%2,%3};"
                 : "+f"(c[0]), "+f"(c[1]), "+f"(c[2]), "+f"(c[3])
                 : "r"(a[0]), "r"(a[1]), "r"(a[2]), "r"(a[3]), "r"(b[0]), "r"(b[1]));
}
__device__ __forceinline__ uint32_t cvt2(float a, float b) {
    __half2 t = __floats2half2_rn(a, b);
    return *(uint32_t*)&t;
}

// ======================= GEMM common: BK=64, 2-stage, 8 warps (64x32 warp tile) =======================
#define GSTR   144                      // bytes per smem row (64 fp16 + 8 pad)
#define TILE_B (128 * GSTR)             // 18432 B
#define SLAB_B (2 * TILE_B)             // 36864 B (A tile + B tile)
#define GEMM_SMEM (2 * SLAB_B)          // 73728 B (2 stages)

// loads one 128x64 fp16 tile pair (A rows, B rows) for k-slab KS into stage ST
#define LOAD_SLAB(ST, KS) do {                                                \
        const uint32_t _sb = smb + (ST) * SLAB_B;                             \
        const int _ko = (KS) * 64;                                            \
        _Pragma("unroll")                                                     \
        for (int t = 0; t < 2; t++) {                                         \
            const fp16* g = src[t] + _ko;                                     \
            const uint32_t tb = _sb + t * TILE_B;                             \
            _Pragma("unroll")                                                 \
            for (int u = 0; u < 4; u++) {                                     \
                int p = tid + u * 256;                                        \
                int r = p >> 3, c = p & 7;                                    \
                cp16(tb + (uint32_t)(r * GSTR + c * 16),                      \
                     g + (size_t)r * K + c * 8);                              \
            }                                                                 \
        }                                                                     \
        CP_COMMIT();                                                          \
    } while (0)

// mainloop body: accumulates one 64-K slab from stage `st` into acc
#define GEMM_SLAB_MMA(ST) do {                                                \
        const uint32_t ab = smb + (ST) * SLAB_B;                              \
        const uint32_t bb = ab + TILE_B;                                      \
        _Pragma("unroll")                                                     \
        for (int kk = 0; kk < 4; kk++) {                                      \
            const uint32_t koff = kk * 32 + lcol16;                           \
            uint32_t af[4][4];                                                \
            _Pragma("unroll")                                                 \
            for (int mi = 0; mi < 4; mi++) {                                  \
                uint32_t ra = (uint32_t)((warp_m * 64 + mi * 16 + lrow) * GSTR) + koff; \
                ldm_x4(af[mi][0], af[mi][1], af[mi][2], af[mi][3], ab + ra);  \
            }                                                                 \
            uint32_t bf[4][2];                                                \
            _Pragma("unroll")                                                 \
            for (int nt = 0; nt < 2; nt++) {                                  \
                uint32_t rb = (uint32_t)((warp_n * 32 + nt * 16 + lrow) * GSTR) + koff; \
                uint32_t r0, r1, r2, r3;                                      \
                ldm_x4(r0, r1, r2, r3, bb + rb);                              \
                bf[nt * 2 + 0][0] = r0; bf[nt * 2 + 0][1] = r2;               \
                bf[nt * 2 + 1][0] = r1; bf[nt * 2 + 1][1] = r3;               \
            }                                                                 \
            _Pragma("unroll")                                                 \
            for (int mi = 0; mi < 4; mi++)                                    \
                _Pragma("unroll")                                             \
                for (int ni = 0; ni < 4; ni++)                                \
                    mma16816(acc[mi][ni], af[mi], bf[ni]);                    \
        }                                                                     \
    } while (0)

#define GEMM_PROLOG()                                                         \
    extern __shared__ char sm[];                                              \
    const uint32_t smb = smem_u32(sm);                                        \
    const int tid = threadIdx.x;                                              \
    const int wid = tid >> 5;                                                 \
    const int lid = tid & 31;                                                 \
    const int warp_m = wid >> 2;                                              \
    const int warp_n = wid & 3;                                               \
    const uint32_t lrow = (uint32_t)(lid & 15);                               \
    const uint32_t lcol16 = (uint32_t)(lid >> 4) * 16;                        \
    float acc[4][4][4];                                                       \
    _Pragma("unroll")                                                         \
    for (int i = 0; i < 4; i++)                                               \
        _Pragma("unroll")                                                     \
        for (int j = 0; j < 4; j++)                                           \
            _Pragma("unroll")                                                 \
            for (int f = 0; f < 4; f++) acc[i][j][f] = 0.f;

#define GEMM_MAINLOOP()                                                       \
    const int NS = K / 64;                                                    \
    LOAD_SLAB(0, 0);                                                          \
    int st = 0;                                                               \
    for (int s = 0; s < NS; s++) {                                            \
        if (s + 1 < NS) { LOAD_SLAB(st ^ 1, s + 1); CP_WAIT1(); }             \
        else            { CP_WAIT0(); }                                       \
        __syncthreads();                                                      \
        GEMM_SLAB_MMA(st);                                                    \
        __syncthreads();                                                      \
        st ^= 1;                                                              \
    }

// ======================= generic GEMM (Wo / W1 / W2 paths) =======================
__global__ __launch_bounds__(256, 2) void mma_gemm(
    const fp16* __restrict__ A, const fp16* __restrict__ B,
    const float* __restrict__ bias, const float* __restrict__ R,
    float* __restrict__ outF, fp16* __restrict__ outH,
    int M, int N, int K, int mode)
{
    GEMM_PROLOG();
    const int row0 = blockIdx.y * 128;
    const int col0 = blockIdx.x * 128;
    const fp16* src[2];
    src[0] = A + (size_t)row0 * K;
    src[1] = B + (size_t)col0 * K;
    GEMM_MAINLOOP();

    const int qr = lid >> 2;
    const int qc = (lid & 3) * 2;
#pragma unroll
    for (int mi = 0; mi < 4; mi++) {
#pragma unroll
        for (int ni = 0; ni < 4; ni++) {
            const int n = col0 + warp_n * 32 + ni * 8 + qc;
            const float b0 = bias[n], b1 = bias[n + 1];
#pragma unroll
            for (int half = 0; half < 2; half++) {
                const int m = row0 + warp_m * 64 + mi * 16 + qr + half * 8;
                float v0 = acc[mi][ni][half * 2 + 0] + b0;
                float v1 = acc[mi][ni][half * 2 + 1] + b1;
                if (mode == MODE_RES) {
                    const float* rp = &R[(size_t)m * N + n];
                    v0 += rp[0]; v1 += rp[1];
                    float2 o2 = {v0, v1};
                    *(float2*)&outF[(size_t)m * N + n] = o2;
                } else { // MODE_RELU_H
                    v0 = fmaxf(v0, 0.f); v1 = fmaxf(v1, 0.f);
                    *(__half2*)&outH[(size_t)m * N + n] = __floats2half2_rn(v0, v1);
                }
            }
        }
    }
}

// ======================= fused QKV GEMM =======================
// grid.x = 24: blocks 0..7 compute Q = xh @ Wq^T; blocks 8..23 compute [K;V] = yh @ Wkv^T.
// Outputs land in [B,H,S,DK] fp16.
__global__ __launch_bounds__(256, 2) void mma_qkv(
    const fp16* __restrict__ Aq, const fp16* __restrict__ Akv,
    const fp16* __restrict__ Bq, const fp16* __restrict__ Bkv,
    const float* __restrict__ bq, const float* __restrict__ bk, const float* __restrict__ bv,
    fp16* __restrict__ qh, fp16* __restrict__ kh, fp16* __restrict__ vh,
    int K)
{
    GEMM_PROLOG();
    const bool isQ = (blockIdx.x < 8);
    const int row0 = blockIdx.y * 128;
    const int col0 = (isQ ? blockIdx.x : (blockIdx.x - 8)) * 128;
    const fp16* src[2];
    src[0] = (isQ ? Aq : Akv) + (size_t)row0 * K;
    src[1] = (isQ ? Bq : Bkv) + (size_t)col0 * K;
    GEMM_MAINLOOP();

    const int qr = lid >> 2;
    const int qc = (lid & 3) * 2;
#pragma unroll
    for (int mi = 0; mi < 4; mi++) {
#pragma unroll
        for (int ni = 0; ni < 4; ni++) {
            const int n = col0 + warp_n * 32 + ni * 8 + qc;
            fp16* dst; const float* bp; int nn;
            if (isQ)           { dst = qh; bp = bq; nn = n; }
            else if (n < BDIM) { dst = kh; bp = bk; nn = n; }
            else               { dst = vh; bp = bv; nn = n - BDIM; }
            const float b0 = bp[nn], b1 = bp[nn + 1];
#pragma unroll
            for (int half = 0; half < 2; half++) {
                const int m = row0 + warp_m * 64 + mi * 16 + qr + half * 8;
                float v0 = acc[mi][ni][half * 2 + 0] + b0;
                float v1 = acc[mi][ni][half * 2 + 1] + b1;
                int hh = nn >> 6, dk = nn & 63, bb = m >> 11, ss = m & 2047;
                size_t o = (((size_t)(bb * NH + hh)) * SEQ + ss) * DKH + dk;
                *(__half2*)&dst[o] = __floats2half2_rn(v0, v1);
            }
        }
    }
}

// ======================= tensor-core flash attention (fp16, single-pass) =======================
#define AT_STRIDE 144
#define AT_TILE   (64 * AT_STRIDE)            // 9216 B per 64x64 fp16 tile
#define AT_STAGE  (2 * AT_TILE)               // K, V
#define AT_MSK    (2 * AT_STAGE)              // 36864
#define AT_SMEM   (AT_MSK + 512)

__global__ __launch_bounds__(256, 2) void attn_tc(
    const fp16* __restrict__ Qg, const fp16* __restrict__ Kg,
    const fp16* __restrict__ Vg, const int* __restrict__ mask,
    fp16* __restrict__ O_out)
{
    extern __shared__ char sm[];
    const uint32_t smb = smem_u32(sm);
    const int tid = threadIdx.x;
    const int wid = tid >> 5;
    const int lid = tid & 31;
    const int q0  = blockIdx.x * 128;
    const int h   = blockIdx.y;
    const int bz  = blockIdx.z;
    const size_t hoff = ((size_t)(bz * NH + h)) * SEQ * DKH;

    const uint32_t lr   = (uint32_t)(lid & 15);
    const uint32_t lc16 = (uint32_t)(lid >> 4) * 16;

    // ---- Q tile -> smem, then register fragments ----
    {
        const fp16* qh = Qg + hoff + (size_t)q0 * DKH;
#pragma unroll
        for (int u = 0; u < 4; u++) {
            int p = tid + u * 256;
            int r = p >> 3, c = p & 7;
            cp16(smb + (uint32_t)(r * AT_STRIDE + c * 16), qh + (size_t)r * DKH + c * 8);
        }
        CP_COMMIT(); CP_WAIT0();
    }
    __syncthreads();
    uint32_t qf[4][4];
#pragma unroll
    for (int ks = 0; ks < 4; ks++) {
        uint32_t ra = (uint32_t)((wid * 16 + lr) * AT_STRIDE) + ks * 32 + lc16;
        ldm_x4(qf[ks][0], qf[ks][1], qf[ks][2], qf[ks][3], smb + ra);
    }
    __syncthreads();

    float O[8][4];
#pragma unroll
    for (int i = 0; i < 8; i++)
#pragma unroll
        for (int j = 0; j < 4; j++) O[i][j] = 0.f;
    float m0 = -INFINITY, m1 = -INFINITY, l0 = 0.f, l1 = 0.f;

    const fp16* kg = Kg + hoff;
    const fp16* vg = Vg + hoff;
    const int*  mkg = mask + bz * SEQ;

#define LOAD_KV(ST, T) do {                                                     \
        const uint32_t _sb = smb + (ST) * AT_STAGE;                             \
        const int _k0 = (T) * 64;                                               \
        _Pragma("unroll")                                                       \
        for (int u = 0; u < 2; u++) {                                           \
            int p = tid + u * 256;                                              \
            int r = p >> 3, c = p & 7;                                          \
            uint32_t so = (uint32_t)(r * AT_STRIDE + c * 16);                   \
            size_t go = (size_t)(_k0 + r) * DKH + c * 8;                        \
            cp16(_sb + so, kg + go);                                            \
            cp16(_sb + AT_TILE + so, vg + go);                                  \
        }                                                                       \
        if (tid < 16) cp16(smb + AT_MSK + (ST) * 256 + tid * 16, mkg + _k0 + tid * 4); \
        CP_COMMIT();                                                            \
    } while (0)

    LOAD_KV(0, 0);

    for (int t = 0; t < SEQ / 64; t++) {
        const int st = t & 1;
        if (t + 1 < SEQ / 64) { LOAD_KV(st ^ 1, t + 1); CP_WAIT1(); }
        else                  { CP_WAIT0(); }
        __syncthreads();

        const uint32_t sb = smb + st * AT_STAGE;
        const int* msk = (const int*)(sm + AT_MSK + st * 256);

        float s[8][4];
#pragma unroll
        for (int i = 0; i < 8; i++)
#pragma unroll
            for (int j = 0; j < 4; j++) s[i][j] = 0.f;

#pragma unroll
        for (int ks = 0; ks < 4; ks++) {
            const uint32_t koff = ks * 32 + lc16;
#pragma unroll
            for (int g = 0; g < 4; g++) {
                uint32_t rb = (uint32_t)((g * 16 + lr) * AT_STRIDE) + koff;
                uint32_t r0, r1, r2, r3;
                ldm_x4(r0, r1, r2, r3, sb + rb);
                uint32_t b0[2] = {r0, r2}, b1[2] = {r1, r3};
                mma16816(s[2 * g],     qf[ks], b0);
                mma16816(s[2 * g + 1], qf[ks], b1);
            }
        }

#pragma unroll
        for (int j = 0; j < 8; j++) {
            int c0 = j * 8 + (lid & 3) * 2;
            bool z0 = (msk[c0] == 0), z1 = (msk[c0 + 1] == 0);
            s[j][0] = z0 ? -1e9f : s[j][0] * 0.125f;
            s[j][2] = z0 ? -1e9f : s[j][2] * 0.125f;
            s[j][1] = z1 ? -1e9f : s[j][1] * 0.125f;
            s[j][3] = z1 ? -1e9f : s[j][3] * 0.125f;
        }

        float mx0 = -INFINITY, mx1 = -INFINITY;
#pragma unroll
        for (int j = 0; j < 8; j++) {
            mx0 = fmaxf(mx0, fmaxf(s[j][0], s[j][1]));
            mx1 = fmaxf(mx1, fmaxf(s[j][2], s[j][3]));
        }
#pragma unroll
        for (int off = 1; off <= 2; off <<= 1) {
            mx0 = fmaxf(mx0, __shfl_xor_sync(0xffffffffu, mx0, off));
            mx1 = fmaxf(mx1, __shfl_xor_sync(0xffffffffu, mx1, off));
        }
        float nm0 = fmaxf(m0, mx0), nm1 = fmaxf(m1, mx1);
        float a0 = __expf(m0 - nm0), a1 = __expf(m1 - nm1);
        float sum0 = 0.f, sum1 = 0.f;
#pragma unroll
        for (int j = 0; j < 8; j++) {
            s[j][0] = __expf(s[j][0] - nm0); sum0 += s[j][0];
            s[j][1] = __expf(s[j][1] - nm0); sum0 += s[j][1];
            s[j][2] = __expf(s[j][2] - nm1); sum1 += s[j][2];
            s[j][3] = __expf(s[j][3] - nm1); sum1 += s[j][3];
        }
#pragma unroll
        for (int off = 1; off <= 2; off <<= 1) {
            sum0 += __shfl_xor_sync(0xffffffffu, sum0, off);
            sum1 += __shfl_xor_sync(0xffffffffu, sum1, off);
        }
        l0 = l0 * a0 + sum0;
        l1 = l1 * a1 + sum1;
        m0 = nm0; m1 = nm1;
#pragma unroll
        for (int i = 0; i < 8; i++) {
            O[i][0] *= a0; O[i][1] *= a0;
            O[i][2] *= a1; O[i][3] *= a1;
        }

#pragma unroll
        for (int j = 0; j < 4; j++) {
            uint32_t P[4];
            P[0] = cvt2(s[2 * j][0],     s[2 * j][1]);
            P[1] = cvt2(s[2 * j][2],     s[2 * j][3]);
            P[2] = cvt2(s[2 * j + 1][0], s[2 * j + 1][1]);
            P[3] = cvt2(s[2 * j + 1][2], s[2 * j + 1][3]);
#pragma unroll
            for (int c = 0; c < 4; c++) {
                uint32_t r0, r1, r2, r3;
                ldm_x4_t(r0, r1, r2, r3,
                         sb + AT_TILE + (uint32_t)((j * 16 + lr) * AT_STRIDE) + c * 32 + lc16);
                uint32_t B0[2] = {r0, r1}, B1[2] = {r2, r3};
                mma16816(O[2 * c],     P, B0);
                mma16816(O[2 * c + 1], P, B1);
            }
        }
        __syncthreads();
    }

    const float il0 = 1.f / (l0 > 0.f ? l0 : 1.f);
    const float il1 = 1.f / (l1 > 0.f ? l1 : 1.f);
    const int qr  = q0 + wid * 16 + (lid >> 2);
    const int col0 = h * DKH + (lid & 3) * 2;
#pragma unroll
    for (int nt = 0; nt < 8; nt++) {
        const int col = col0 + nt * 8;
        {
            __half2 p = __floats2half2_rn(O[nt][0] * il0, O[nt][1] * il0);
            *(__half2*)&O_out[((size_t)bz * SEQ + qr) * BDIM + col] = p;
        }
        {
            __half2 p = __floats2half2_rn(O[nt][2] * il1, O[nt][3] * il1);
            *(__half2*)&O_out[((size_t)bz * SEQ + qr + 8) * BDIM + col] = p;
        }
    }
}

// ======================= batched weight transpose (4x D*D, fp32 -> fp16 [N,K]) =======================
__global__ __launch_bounds__(256) void wtrans4_kernel(
    const float* __restrict__ W0, const float* __restrict__ W1_,
    const float* __restrict__ W2_, const float* __restrict__ W3_,
    fp16* __restrict__ T0, fp16* __restrict__ T1,
    fp16* __restrict__ T2, fp16* __restrict__ T3)
{
    __shared__ float t[32][33];
    const int z = blockIdx.z;
    const float* W = (z == 0) ? W0 : (z == 1) ? W1_ : (z == 2) ? W2_ : W3_;
    fp16* T = (z == 0) ? T0 : (z == 1) ? T1 : (z == 2) ? T2 : T3;
    const int n0 = blockIdx.x * 32, k0 = blockIdx.y * 32;
    const int tx = threadIdx.x, ty = threadIdx.y;
#pragma unroll
    for (int j = 0; j < 4; j++)
        t[ty + j * 8][tx] = W[(size_t)(k0 + ty + j * 8) * BDIM + n0 + tx];
    __syncthreads();
#pragma unroll
    for (int j = 0; j < 4; j++)
        T[(size_t)(n0 + ty + j * 8) * BDIM + k0 + tx] = __float2half(t[tx][ty + j * 8]);
}

// ======================= batched W1/W2 transpose =======================
// z=0: W1 [1024,4096] -> w1T[4096,1024]; z=1: W2 [4096,1024] -> w2T[1024,4096]
__global__ __launch_bounds__(256) void wtrans2_kernel(
    const float* __restrict__ W1g, fp16* __restrict__ T1g,
    const float* __restrict__ W2g, fp16* __restrict__ T2g)
{
    __shared__ float t[32][33];
    const int z = blockIdx.z;
    const float* W = z ? W2g : W1g;
    fp16* T = z ? T2g : T1g;
    // z=0: K=1024,N=4096: n0 = bx*32 (128 blocks), k0 = by*32 (32 blocks)
    // z=1: K=4096,N=1024: k0 = bx*32 (128 blocks), n0 = by*32 (32 blocks)
    const int n0 = (z ? blockIdx.y : blockIdx.x) * 32;
    const int k0 = (z ? blockIdx.x : blockIdx.y) * 32;
    const int K = z ? HIDN : BDIM;
    const int N = z ? BDIM : HIDN;
    const int tx = threadIdx.x, ty = threadIdx.y;
#pragma unroll
    for (int j = 0; j < 4; j++)
        t[ty + j * 8][tx] = W[(size_t)(k0 + ty + j * 8) * N + n0 + tx];
    __syncthreads();
#pragma unroll
    for (int j = 0; j < 4; j++)
        T[(size_t)(n0 + ty + j * 8) * K + k0 + tx] = __float2half(t[tx][ty + j * 8]);
}

// ======================= fp32 -> fp16 (batched x & y) =======================
__global__ __launch_bounds__(256) void cvt_h2(
    const float* __restrict__ X, fp16* __restrict__ HX,
    const float* __restrict__ Y, fp16* __restrict__ HY)
{
    const float* S = blockIdx.y ? Y : X;
    fp16* Dd = blockIdx.y ? HY : HX;
    const int i = (blockIdx.x * 256 + threadIdx.x) * 4;
    const float4 v = *(const float4*)(S + i);
    *(__half2*)(Dd + i)     = __floats2half2_rn(v.x, v.y);
    *(__half2*)(Dd + i + 2) = __floats2half2_rn(v.z, v.w);
}

// ======================= LayerNorm (+ optional fp16 output) =======================
__global__ __launch_bounds__(256) void ln_kernel(
    const float* __restrict__ X, const float* __restrict__ g,
    const float* __restrict__ b, float* __restrict__ Y, fp16* __restrict__ Yh)
{
    __shared__ float red[2][8];
    __shared__ float stats[2];
    const int row = blockIdx.x;
    const int tid = threadIdx.x;

    const float4 v = ((const float4*)(X + (size_t)row * BDIM))[tid];
    float s = v.x + v.y + v.z + v.w;
    float q = v.x * v.x + v.y * v.y + v.z * v.z + v.w * v.w;
#pragma unroll
    for (int o = 16; o > 0; o >>= 1) {
        s += __shfl_xor_sync(0xffffffffu, s, o);
        q += __shfl_xor_sync(0xffffffffu, q, o);
    }
    const int lane = tid & 31, w = tid >> 5;
    if (lane == 0) { red[0][w] = s; red[1][w] = q; }
    __syncthreads();
    if (tid < 32) {
        s = (tid < 8) ? red[0][tid] : 0.f;
        q = (tid < 8) ? red[1][tid] : 0.f;
#pragma unroll
        for (int o = 4; o > 0; o >>= 1) {
            s += __shfl_xor_sync(0xffffffffu, s, o);
            q += __shfl_xor_sync(0xffffffffu, q, o);
        }
        if (tid == 0) {
            float mean = s * (1.f / BDIM);
            stats[0] = mean;
            stats[1] = rsqrtf(q * (1.f / BDIM) - mean * mean + 1e-5f);
        }
    }
    __syncthreads();
    const float mean = stats[0], rinv = stats[1];
    const float4 gg = ((const float4*)g)[tid];
    const float4 bb = ((const float4*)b)[tid];
    float4 o4;
    o4.x = (v.x - mean) * rinv * gg.x + bb.x;
    o4.y = (v.y - mean) * rinv * gg.y + bb.y;
    o4.z = (v.z - mean) * rinv * gg.z + bb.z;
    o4.w = (v.w - mean) * rinv * gg.w + bb.w;
    if (Y) ((float4*)(Y + (size_t)row * BDIM))[tid] = o4;
    if (Yh) {
        size_t base = (size_t)row * BDIM + tid * 4;
        *(__half2*)(Yh + base)     = __floats2half2_rn(o4.x, o4.y);
        *(__half2*)(Yh + base + 2) = __floats2half2_rn(o4.z, o4.w);
    }
}

// ======================= launcher =======================
extern "C" void kernel_launch(void* const* d_in, const int* in_sizes, int n_in,
                              void* d_out, int out_size)
{
    const float* x    = (const float*)d_in[0];
    const float* y    = (const float*)d_in[1];
    const int*   mask = (const int*)  d_in[2];
    const float* Wq = (const float*)d_in[3];  const float* bq = (const float*)d_in[4];
    const float* Wk = (const float*)d_in[5];  const float* bk = (const float*)d_in[6];
    const float* Wv = (const float*)d_in[7];  const float* bv = (const float*)d_in[8];
    const float* Wo = (const float*)d_in[9];  const float* bo = (const float*)d_in[10];
    const float* W1 = (const float*)d_in[11]; const float* b1 = (const float*)d_in[12];
    const float* W2 = (const float*)d_in[13]; const float* b2 = (const float*)d_in[14];
    const float* g1 = (const float*)d_in[15]; const float* be1 = (const float*)d_in[16];
    const float* g2 = (const float*)d_in[17]; const float* be2 = (const float*)d_in[18];
    float* out = (float*)d_out;

    float *s1p, *x1p, *s2p;
    fp16 *xh, *yh, *qh, *kh, *vh, *ah, *x1h, *hh;
    fp16 *wq, *wkv, *wo, *w1, *w2;
    cudaGetSymbolAddress((void**)&s1p, g_s1);  cudaGetSymbolAddress((void**)&x1p, g_x1);
    cudaGetSymbolAddress((void**)&s2p, g_s2);
    cudaGetSymbolAddress((void**)&xh, g_xh);   cudaGetSymbolAddress((void**)&yh, g_yh);
    cudaGetSymbolAddress((void**)&qh, g_Qh);   cudaGetSymbolAddress((void**)&kh, g_Kh);
    cudaGetSymbolAddress((void**)&vh, g_Vh);   cudaGetSymbolAddress((void**)&ah, g_ah);
    cudaGetSymbolAddress((void**)&x1h, g_x1h); cudaGetSymbolAddress((void**)&hh, g_hh);
    cudaGetSymbolAddress((void**)&wq, g_wqT);  cudaGetSymbolAddress((void**)&wkv, g_wkvT);
    cudaGetSymbolAddress((void**)&wo, g_woT);
    cudaGetSymbolAddress((void**)&w1, g_w1T);  cudaGetSymbolAddress((void**)&w2, g_w2T);

    cudaFuncSetAttribute(mma_gemm, cudaFuncAttributeMaxDynamicSharedMemorySize, GEMM_SMEM);
    cudaFuncSetAttribute(mma_qkv,  cudaFuncAttributeMaxDynamicSharedMemorySize, GEMM_SMEM);
    cudaFuncSetAttribute(attn_tc,  cudaFuncAttributeMaxDynamicSharedMemorySize, AT_SMEM);

    // ---- weight prep: 2 batched launches ----
    dim3 tb(32, 8);
    wtrans4_kernel<<<dim3(BDIM / 32, BDIM / 32, 4), tb>>>(
        Wq, Wk, Wv, Wo, wq, wkv, wkv + (size_t)BDIM * BDIM, wo);
    wtrans2_kernel<<<dim3(HIDN / 32, BDIM / 32, 2), tb>>>(W1, w1, W2, w2);

    // ---- activation fp16 conversion (x and y in one launch) ----
    cvt_h2<<<dim3((MROWS * BDIM) / 1024, 2), 256>>>(x, xh, y, yh);

    dim3 gD(BDIM / 128, MROWS / 128);          // 8 x 32
    dim3 gQKV(3 * BDIM / 128, MROWS / 128);    // 24 x 32 = 768 CTAs (fused Q+K+V)
    dim3 gH(HIDN / 128, MROWS / 128);          // 32 x 32

    // fused QKV projections -> [B,H,S,DK] fp16
    mma_qkv<<<gQKV, 256, GEMM_SMEM>>>(xh, yh, wq, wkv, bq, bk, bv, qh, kh, vh, BDIM);

    // tensor-core flash attention -> fp16 [B,S,D]
    attn_tc<<<dim3(SEQ / 128, NH, NB), 256, AT_SMEM>>>(qh, kh, vh, mask, ah);

    // s1 = x + attn @ Wo + bo ; x1 = LN(s1) (+fp16)
    mma_gemm<<<gD, 256, GEMM_SMEM>>>(ah, wo, bo, x, s1p, nullptr, MROWS, BDIM, BDIM, MODE_RES);
    ln_kernel<<<MROWS, 256>>>(s1p, g1, be1, x1p, x1h);

    // FFN
    mma_gemm<<<gH, 256, GEMM_SMEM>>>(x1h, w1, b1, nullptr, nullptr, hh, MROWS, HIDN, BDIM, MODE_RELU_H);
    mma_gemm<<<gD, 256, GEMM_SMEM>>>(hh, w2, b2, x1p, s2p, nullptr, MROWS, BDIM, HIDN, MODE_RES);
    ln_kernel<<<MROWS, 256>>>(s2p, g2, be2, out, nullptr);
}

// round 14
// speedup vs baseline: 1.1343x; 1.0104x over previous
#include <cuda_runtime.h>
#include <cuda_fp16.h>
#include <math.h>
#include <stdint.h>

#define BDIM 1024
#define SEQ  2048
#define NH   16
#define DKH  64
#define HIDN 4096
#define MROWS 4096   // B*S
#define NB   2

typedef __half fp16;

// ---------------- scratch (static device globals; no allocation) ----------------
__device__ float g_s1 [MROWS * BDIM];
__device__ float g_x1 [MROWS * BDIM];
__device__ float g_s2 [MROWS * BDIM];

__device__ fp16 g_xh  [MROWS * BDIM];
__device__ fp16 g_yh  [MROWS * BDIM];
__device__ fp16 g_Qh  [MROWS * BDIM];   // [B,H,S,DK]
__device__ fp16 g_Kh  [MROWS * BDIM];
__device__ fp16 g_Vh  [MROWS * BDIM];
__device__ fp16 g_ah  [MROWS * BDIM];   // attention output [B,S,D]
__device__ fp16 g_x1h [MROWS * BDIM];
__device__ fp16 g_hh  [MROWS * HIDN];

// transposed weights: Wt[N][K] fp16
__device__ fp16 g_wqT [BDIM * BDIM];
__device__ fp16 g_wkvT[2 * BDIM * BDIM];   // [Wk^T ; Wv^T]
__device__ fp16 g_woT [BDIM * BDIM];
__device__ fp16 g_w1T [HIDN * BDIM];
__device__ fp16 g_w2T [BDIM * HIDN];

enum { MODE_RELU_H = 1, MODE_RES = 2 };

// ======================= PTX helpers =======================
__device__ __forceinline__ uint32_t smem_u32(const void* p) {
    uint32_t a;
    asm("{ .reg .u64 t; cvta.to.shared.u64 t, %1; cvt.u32.u64 %0, t; }" : "=r"(a) : "l"(p));
    return a;
}
__device__ __forceinline__ void cp16(uint32_t s, const void* g) {
    asm volatile("cp.async.cg.shared.global [%0], [%1], 16;" :: "r"(s), "l"(g));
}
#define CP_COMMIT() asm volatile("cp.async.commit_group;" ::: "memory")
#define CP_WAIT0()  asm volatile("cp.async.wait_group 0;" ::: "memory")
#define CP_WAIT1()  asm volatile("cp.async.wait_group 1;" ::: "memory")

__device__ __forceinline__ void ldm_x4(uint32_t& r0, uint32_t& r1, uint32_t& r2, uint32_t& r3, uint32_t a) {
    asm volatile("ldmatrix.sync.aligned.m8n8.x4.shared.b16 {%0,%1,%2,%3}, [%4];"
                 : "=r"(r0), "=r"(r1), "=r"(r2), "=r"(r3) : "r"(a));
}
__device__ __forceinline__ void ldm_x4_t(uint32_t& r0, uint32_t& r1, uint32_t& r2, uint32_t& r3, uint32_t a) {
    asm volatile("ldmatrix.sync.aligned.m8n8.x4.trans.shared.b16 {%0,%1,%2,%3}, [%4];"
                 : "=r"(r0), "=r"(r1), "=r"(r2), "=r"(r3) : "r"(a));
}
__device__ __forceinline__ void mma16816(float* c, const uint32_t* a, const uint32_t* b) {
    asm volatile("mma.sync.aligned.m16n8k16.row.col.f32.f16.f16.f32 "
                 "{%0,%1,%2,%3}, {%4,%5,%6,%7}, {%8,%9}, {%0,%1,%2,%3};"
                 : "+f"(c[0]), "+f"(c[1]), "+f"(c[2]), "+f"(c[3])
                 : "r"(a[0]), "r"(a[1]), "r"(a[2]), "r"(a[3]), "r"(b[0]), "r"(b[1]));
}
__device__ __forceinline__ uint32_t cvt2(float a, float b) {
    __half2 t = __floats2half2_rn(a, b);
    return *(uint32_t*)&t;
}
__device__ __forceinline__ float ex2f(float x) {
    float y;
    asm("ex2.approx.f32 %0, %1;" : "=f"(y) : "f"(x));
    return y;
}

// ======================= GEMM common: BK=64, 2-stage, 8 warps (64x32 warp tile) =======================
#define GSTR   144                      // bytes per smem row (64 fp16 + 8 pad)
#define TILE_B (128 * GSTR)             // 18432 B
#define SLAB_B (2 * TILE_B)             // 36864 B (A tile + B tile)
#define GEMM_SMEM (2 * SLAB_B)          // 73728 B (2 stages)

#define LOAD_SLAB(ST, KS) do {                                                \
        const uint32_t _sb = smb + (ST) * SLAB_B;                             \
        const int _ko = (KS) * 64;                                            \
        _Pragma("unroll")                                                     \
        for (int t = 0; t < 2; t++) {                                         \
            const fp16* g = src[t] + _ko;                                     \
            const uint32_t tb = _sb + t * TILE_B;                             \
            _Pragma("unroll")                                                 \
            for (int u = 0; u < 4; u++) {                                     \
                int p = tid + u * 256;                                        \
                int r = p >> 3, c = p & 7;                                    \
                cp16(tb + (uint32_t)(r * GSTR + c * 16),                      \
                     g + (size_t)r * K + c * 8);                              \
            }                                                                 \
        }                                                                     \
        CP_COMMIT();                                                          \
    } while (0)

#define GEMM_SLAB_MMA(ST) do {                                                \
        const uint32_t ab = smb + (ST) * SLAB_B;                              \
        const uint32_t bb = ab + TILE_B;                                      \
        _Pragma("unroll")                                                     \
        for (int kk = 0; kk < 4; kk++) {                                      \
            const uint32_t koff = kk * 32 + lcol16;                           \
            uint32_t af[4][4];                                                \
            _Pragma("unroll")                                                 \
            for (int mi = 0; mi < 4; mi++) {                                  \
                uint32_t ra = (uint32_t)((warp_m * 64 + mi * 16 + lrow) * GSTR) + koff; \
                ldm_x4(af[mi][0], af[mi][1], af[mi][2], af[mi][3], ab + ra);  \
            }                                                                 \
            uint32_t bf[4][2];                                                \
            _Pragma("unroll")                                                 \
            for (int nt = 0; nt < 2; nt++) {                                  \
                uint32_t rb = (uint32_t)((warp_n * 32 + nt * 16 + lrow) * GSTR) + koff; \
                uint32_t r0, r1, r2, r3;                                      \
                ldm_x4(r0, r1, r2, r3, bb + rb);                              \
                bf[nt * 2 + 0][0] = r0; bf[nt * 2 + 0][1] = r2;               \
                bf[nt * 2 + 1][0] = r1; bf[nt * 2 + 1][1] = r3;               \
            }                                                                 \
            _Pragma("unroll")                                                 \
            for (int mi = 0; mi < 4; mi++)                                    \
                _Pragma("unroll")                                             \
                for (int ni = 0; ni < 4; ni++)                                \
                    mma16816(acc[mi][ni], af[mi], bf[ni]);                    \
        }                                                                     \
    } while (0)

#define GEMM_PROLOG()                                                         \
    extern __shared__ char sm[];                                              \
    const uint32_t smb = smem_u32(sm);                                        \
    const int tid = threadIdx.x;                                              \
    const int wid = tid >> 5;                                                 \
    const int lid = tid & 31;                                                 \
    const int warp_m = wid >> 2;                                              \
    const int warp_n = wid & 3;                                               \
    const uint32_t lrow = (uint32_t)(lid & 15);                               \
    const uint32_t lcol16 = (uint32_t)(lid >> 4) * 16;                        \
    float acc[4][4][4];                                                       \
    _Pragma("unroll")                                                         \
    for (int i = 0; i < 4; i++)                                               \
        _Pragma("unroll")                                                     \
        for (int j = 0; j < 4; j++)                                           \
            _Pragma("unroll")                                                 \
            for (int f = 0; f < 4; f++) acc[i][j][f] = 0.f;

#define GEMM_MAINLOOP()                                                       \
    const int NS = K / 64;                                                    \
    LOAD_SLAB(0, 0);                                                          \
    int st = 0;                                                               \
    for (int s = 0; s < NS; s++) {                                            \
        if (s + 1 < NS) { LOAD_SLAB(st ^ 1, s + 1); CP_WAIT1(); }             \
        else            { CP_WAIT0(); }                                       \
        __syncthreads();                                                      \
        GEMM_SLAB_MMA(st);                                                    \
        __syncthreads();                                                      \
        st ^= 1;                                                              \
    }

// ======================= generic GEMM (Wo / W1 / W2 paths) =======================
__global__ __launch_bounds__(256, 2) void mma_gemm(
    const fp16* __restrict__ A, const fp16* __restrict__ B,
    const float* __restrict__ bias, const float* __restrict__ R,
    float* __restrict__ outF, fp16* __restrict__ outH,
    int M, int N, int K, int mode)
{
    GEMM_PROLOG();
    const int row0 = blockIdx.y * 128;
    const int col0 = blockIdx.x * 128;
    const fp16* src[2];
    src[0] = A + (size_t)row0 * K;
    src[1] = B + (size_t)col0 * K;
    GEMM_MAINLOOP();

    const int qr = lid >> 2;
    const int qc = (lid & 3) * 2;
#pragma unroll
    for (int mi = 0; mi < 4; mi++) {
#pragma unroll
        for (int ni = 0; ni < 4; ni++) {
            const int n = col0 + warp_n * 32 + ni * 8 + qc;
            const float b0 = bias[n], b1 = bias[n + 1];
#pragma unroll
            for (int half = 0; half < 2; half++) {
                const int m = row0 + warp_m * 64 + mi * 16 + qr + half * 8;
                float v0 = acc[mi][ni][half * 2 + 0] + b0;
                float v1 = acc[mi][ni][half * 2 + 1] + b1;
                if (mode == MODE_RES) {
                    const float* rp = &R[(size_t)m * N + n];
                    v0 += rp[0]; v1 += rp[1];
                    float2 o2 = {v0, v1};
                    *(float2*)&outF[(size_t)m * N + n] = o2;
                } else { // MODE_RELU_H
                    v0 = fmaxf(v0, 0.f); v1 = fmaxf(v1, 0.f);
                    *(__half2*)&outH[(size_t)m * N + n] = __floats2half2_rn(v0, v1);
                }
            }
        }
    }
}

// ======================= fused QKV GEMM =======================
__global__ __launch_bounds__(256, 2) void mma_qkv(
    const fp16* __restrict__ Aq, const fp16* __restrict__ Akv,
    const fp16* __restrict__ Bq, const fp16* __restrict__ Bkv,
    const float* __restrict__ bq, const float* __restrict__ bk, const float* __restrict__ bv,
    fp16* __restrict__ qh, fp16* __restrict__ kh, fp16* __restrict__ vh,
    int K)
{
    GEMM_PROLOG();
    const bool isQ = (blockIdx.x < 8);
    const int row0 = blockIdx.y * 128;
    const int col0 = (isQ ? blockIdx.x : (blockIdx.x - 8)) * 128;
    const fp16* src[2];
    src[0] = (isQ ? Aq : Akv) + (size_t)row0 * K;
    src[1] = (isQ ? Bq : Bkv) + (size_t)col0 * K;
    GEMM_MAINLOOP();

    const int qr = lid >> 2;
    const int qc = (lid & 3) * 2;
#pragma unroll
    for (int mi = 0; mi < 4; mi++) {
#pragma unroll
        for (int ni = 0; ni < 4; ni++) {
            const int n = col0 + warp_n * 32 + ni * 8 + qc;
            fp16* dst; const float* bp; int nn;
            if (isQ)           { dst = qh; bp = bq; nn = n; }
            else if (n < BDIM) { dst = kh; bp = bk; nn = n; }
            else               { dst = vh; bp = bv; nn = n - BDIM; }
            const float b0 = bp[nn], b1 = bp[nn + 1];
#pragma unroll
            for (int half = 0; half < 2; half++) {
                const int m = row0 + warp_m * 64 + mi * 16 + qr + half * 8;
                float v0 = acc[mi][ni][half * 2 + 0] + b0;
                float v1 = acc[mi][ni][half * 2 + 1] + b1;
                int hh = nn >> 6, dk = nn & 63, bb = m >> 11, ss = m & 2047;
                size_t o = (((size_t)(bb * NH + hh)) * SEQ + ss) * DKH + dk;
                *(__half2*)&dst[o] = __floats2half2_rn(v0, v1);
            }
        }
    }
}

// ======================= tensor-core flash attention (fp16, KV tile 128) =======================
#define AT_STRIDE 144
#define AT_KTILE  (128 * AT_STRIDE)           // 18432 B per 128x64 fp16 tile
#define AT_STAGE  (2 * AT_KTILE)              // K + V = 36864
#define AT_MSKOFF (2 * AT_STAGE)              // 73728
#define AT_SMEM   (AT_MSKOFF + 2 * 512 + 128)

__global__ __launch_bounds__(256, 2) void attn_tc(
    const fp16* __restrict__ Qg, const fp16* __restrict__ Kg,
    const fp16* __restrict__ Vg, const int* __restrict__ mask,
    fp16* __restrict__ O_out)
{
    extern __shared__ char sm[];
    const uint32_t smb = smem_u32(sm);
    const int tid = threadIdx.x;
    const int wid = tid >> 5;
    const int lid = tid & 31;
    const int q0  = blockIdx.x * 128;
    const int h   = blockIdx.y;
    const int bz  = blockIdx.z;
    const size_t hoff = ((size_t)(bz * NH + h)) * SEQ * DKH;

    const uint32_t lr   = (uint32_t)(lid & 15);
    const uint32_t lc16 = (uint32_t)(lid >> 4) * 16;

    // ---- Q tile -> smem (stage-0 K region, consumed before KV loads), then frags ----
    {
        const fp16* qh = Qg + hoff + (size_t)q0 * DKH;
#pragma unroll
        for (int u = 0; u < 4; u++) {
            int p = tid + u * 256;
            int r = p >> 3, c = p & 7;
            cp16(smb + (uint32_t)(r * AT_STRIDE + c * 16), qh + (size_t)r * DKH + c * 8);
        }
        CP_COMMIT(); CP_WAIT0();
    }
    __syncthreads();
    uint32_t qf[4][4];
#pragma unroll
    for (int ks = 0; ks < 4; ks++) {
        uint32_t ra = (uint32_t)((wid * 16 + lr) * AT_STRIDE) + ks * 32 + lc16;
        ldm_x4(qf[ks][0], qf[ks][1], qf[ks][2], qf[ks][3], smb + ra);
    }
    __syncthreads();

    float O[8][4];
#pragma unroll
    for (int i = 0; i < 8; i++)
#pragma unroll
        for (int j = 0; j < 4; j++) O[i][j] = 0.f;
    float m0 = -INFINITY, m1 = -INFINITY, l0 = 0.f, l1 = 0.f;

    const fp16* kg = Kg + hoff;
    const fp16* vg = Vg + hoff;
    const int*  mkg = mask + bz * SEQ;

    // softmax runs in exp2 domain: scores pre-scaled by 0.125 * log2(e)
    const float SCL = 0.125f * 1.44269504f;

#define LOAD_KV(ST, T) do {                                                     \
        const uint32_t _sb = smb + (ST) * AT_STAGE;                             \
        const int _k0 = (T) * 128;                                              \
        _Pragma("unroll")                                                       \
        for (int u = 0; u < 4; u++) {                                           \
            int p = tid + u * 256;                                              \
            int r = p >> 3, c = p & 7;                                          \
            uint32_t so = (uint32_t)(r * AT_STRIDE + c * 16);                   \
            size_t go = (size_t)(_k0 + r) * DKH + c * 8;                        \
            cp16(_sb + so, kg + go);                                            \
            cp16(_sb + AT_KTILE + so, vg + go);                                 \
        }                                                                       \
        if (tid < 32) cp16(smb + AT_MSKOFF + (ST) * 512 + tid * 16, mkg + _k0 + tid * 4); \
        CP_COMMIT();                                                            \
    } while (0)

    LOAD_KV(0, 0);

    for (int t = 0; t < SEQ / 128; t++) {
        const int st = t & 1;
        if (t + 1 < SEQ / 128) { LOAD_KV(st ^ 1, t + 1); CP_WAIT1(); }
        else                   { CP_WAIT0(); }
        __syncthreads();

        const uint32_t kb = smb + st * AT_STAGE;
        const uint32_t vb = kb + AT_KTILE;
        const int* msk = (const int*)(sm + AT_MSKOFF + st * 512);

#pragma unroll
        for (int hf = 0; hf < 2; hf++) {
            const int kr0 = hf * 64;

            // ---- scores: QK^T on 64 KV columns ----
            float s[8][4];
#pragma unroll
            for (int i = 0; i < 8; i++)
#pragma unroll
                for (int j = 0; j < 4; j++) s[i][j] = 0.f;

#pragma unroll
            for (int ks = 0; ks < 4; ks++) {
                const uint32_t koff = ks * 32 + lc16;
#pragma unroll
                for (int g = 0; g < 4; g++) {
                    uint32_t rb = (uint32_t)((kr0 + g * 16 + lr) * AT_STRIDE) + koff;
                    uint32_t r0, r1, r2, r3;
                    ldm_x4(r0, r1, r2, r3, kb + rb);
                    uint32_t b0[2] = {r0, r2}, b1[2] = {r1, r3};
                    mma16816(s[2 * g],     qf[ks], b0);
                    mma16816(s[2 * g + 1], qf[ks], b1);
                }
            }

            // ---- mask + scale (log2 domain) ----
#pragma unroll
            for (int j = 0; j < 8; j++) {
                int c0 = kr0 + j * 8 + (lid & 3) * 2;
                bool z0 = (msk[c0] == 0), z1 = (msk[c0 + 1] == 0);
                s[j][0] = z0 ? -1e9f : s[j][0] * SCL;
                s[j][2] = z0 ? -1e9f : s[j][2] * SCL;
                s[j][1] = z1 ? -1e9f : s[j][1] * SCL;
                s[j][3] = z1 ? -1e9f : s[j][3] * SCL;
            }

            // ---- online softmax (rows r and r+8), exp2 domain ----
            float mx0 = -INFINITY, mx1 = -INFINITY;
#pragma unroll
            for (int j = 0; j < 8; j++) {
                mx0 = fmaxf(mx0, fmaxf(s[j][0], s[j][1]));
                mx1 = fmaxf(mx1, fmaxf(s[j][2], s[j][3]));
            }
#pragma unroll
            for (int off = 1; off <= 2; off <<= 1) {
                mx0 = fmaxf(mx0, __shfl_xor_sync(0xffffffffu, mx0, off));
                mx1 = fmaxf(mx1, __shfl_xor_sync(0xffffffffu, mx1, off));
            }
            float nm0 = fmaxf(m0, mx0), nm1 = fmaxf(m1, mx1);
            float a0 = ex2f(m0 - nm0), a1 = ex2f(m1 - nm1);
            float sum0 = 0.f, sum1 = 0.f;
#pragma unroll
            for (int j = 0; j < 8; j++) {
                s[j][0] = ex2f(s[j][0] - nm0); sum0 += s[j][0];
                s[j][1] = ex2f(s[j][1] - nm0); sum0 += s[j][1];
                s[j][2] = ex2f(s[j][2] - nm1); sum1 += s[j][2];
                s[j][3] = ex2f(s[j][3] - nm1); sum1 += s[j][3];
            }
#pragma unroll
            for (int off = 1; off <= 2; off <<= 1) {
                sum0 += __shfl_xor_sync(0xffffffffu, sum0, off);
                sum1 += __shfl_xor_sync(0xffffffffu, sum1, off);
            }
            l0 = l0 * a0 + sum0;
            l1 = l1 * a1 + sum1;
            m0 = nm0; m1 = nm1;
#pragma unroll
            for (int i = 0; i < 8; i++) {
                O[i][0] *= a0; O[i][1] *= a0;
                O[i][2] *= a1; O[i][3] *= a1;
            }

            // ---- O += P @ V ----
#pragma unroll
            for (int j = 0; j < 4; j++) {
                uint32_t P[4];
                P[0] = cvt2(s[2 * j][0],     s[2 * j][1]);
                P[1] = cvt2(s[2 * j][2],     s[2 * j][3]);
                P[2] = cvt2(s[2 * j + 1][0], s[2 * j + 1][1]);
                P[3] = cvt2(s[2 * j + 1][2], s[2 * j + 1][3]);
#pragma unroll
                for (int c = 0; c < 4; c++) {
                    uint32_t r0, r1, r2, r3;
                    ldm_x4_t(r0, r1, r2, r3,
                             vb + (uint32_t)((kr0 + j * 16 + lr) * AT_STRIDE) + c * 32 + lc16);
                    uint32_t B0[2] = {r0, r1}, B1[2] = {r2, r3};
                    mma16816(O[2 * c],     P, B0);
                    mma16816(O[2 * c + 1], P, B1);
                }
            }
        }
        __syncthreads();
    }

    const float il0 = 1.f / (l0 > 0.f ? l0 : 1.f);
    const float il1 = 1.f / (l1 > 0.f ? l1 : 1.f);
    const int qr  = q0 + wid * 16 + (lid >> 2);
    const int col0 = h * DKH + (lid & 3) * 2;
#pragma unroll
    for (int nt = 0; nt < 8; nt++) {
        const int col = col0 + nt * 8;
        {
            __half2 p = __floats2half2_rn(O[nt][0] * il0, O[nt][1] * il0);
            *(__half2*)&O_out[((size_t)bz * SEQ + qr) * BDIM + col] = p;
        }
        {
            __half2 p = __floats2half2_rn(O[nt][2] * il1, O[nt][3] * il1);
            *(__half2*)&O_out[((size_t)bz * SEQ + qr + 8) * BDIM + col] = p;
        }
    }
}

// ======================= all-in-one weight transpose (6 matrices) =======================
// z 0..3: D x D (Wq, Wk, Wv, Wo) — uses only blockIdx.x < 32.
// z = 4: W1 [1024,4096] -> [4096,1024]; z = 5: W2 [4096,1024] -> [1024,4096].
__global__ __launch_bounds__(256) void wtrans6_kernel(
    const float* __restrict__ Wq, const float* __restrict__ Wk,
    const float* __restrict__ Wv, const float* __restrict__ Wo,
    const float* __restrict__ W1g, const float* __restrict__ W2g,
    fp16* __restrict__ Tq, fp16* __restrict__ Tkv, fp16* __restrict__ To,
    fp16* __restrict__ T1, fp16* __restrict__ T2)
{
    __shared__ float t[32][33];
    const int z = blockIdx.z;
    const float* W; fp16* T; int K, N, n0, k0;
    if (z < 4) {
        if (blockIdx.x >= 32) return;
        W = (z == 0) ? Wq : (z == 1) ? Wk : (z == 2) ? Wv : Wo;
        T = (z == 0) ? Tq : (z == 1) ? Tkv : (z == 2) ? (Tkv + (size_t)BDIM * BDIM) : To;
        K = BDIM; N = BDIM;
        n0 = blockIdx.x * 32; k0 = blockIdx.y * 32;
    } else if (z == 4) {
        W = W1g; T = T1; K = BDIM; N = HIDN;
        n0 = blockIdx.x * 32; k0 = blockIdx.y * 32;
    } else {
        W = W2g; T = T2; K = HIDN; N = BDIM;
        n0 = blockIdx.y * 32; k0 = blockIdx.x * 32;
    }
    const int tx = threadIdx.x, ty = threadIdx.y;
#pragma unroll
    for (int j = 0; j < 4; j++)
        t[ty + j * 8][tx] = W[(size_t)(k0 + ty + j * 8) * N + n0 + tx];
    __syncthreads();
#pragma unroll
    for (int j = 0; j < 4; j++)
        T[(size_t)(n0 + ty + j * 8) * K + k0 + tx] = __float2half(t[tx][ty + j * 8]);
}

// ======================= fp32 -> fp16 (batched x & y, 8 elems/thread) =======================
__global__ __launch_bounds__(256) void cvt_h2(
    const float* __restrict__ X, fp16* __restrict__ HX,
    const float* __restrict__ Y, fp16* __restrict__ HY)
{
    const float* S = blockIdx.y ? Y : X;
    fp16* Dd = blockIdx.y ? HY : HX;
    const int i = (blockIdx.x * 256 + threadIdx.x) * 8;
    const float4 v0 = *(const float4*)(S + i);
    const float4 v1 = *(const float4*)(S + i + 4);
    *(__half2*)(Dd + i)     = __floats2half2_rn(v0.x, v0.y);
    *(__half2*)(Dd + i + 2) = __floats2half2_rn(v0.z, v0.w);
    *(__half2*)(Dd + i + 4) = __floats2half2_rn(v1.x, v1.y);
    *(__half2*)(Dd + i + 6) = __floats2half2_rn(v1.z, v1.w);
}

// ======================= LayerNorm (+ optional fp16 output) =======================
__global__ __launch_bounds__(256) void ln_kernel(
    const float* __restrict__ X, const float* __restrict__ g,
    const float* __restrict__ b, float* __restrict__ Y, fp16* __restrict__ Yh)
{
    __shared__ float red[2][8];
    __shared__ float stats[2];
    const int row = blockIdx.x;
    const int tid = threadIdx.x;

    const float4 v = ((const float4*)(X + (size_t)row * BDIM))[tid];
    float s = v.x + v.y + v.z + v.w;
    float q = v.x * v.x + v.y * v.y + v.z * v.z + v.w * v.w;
#pragma unroll
    for (int o = 16; o > 0; o >>= 1) {
        s += __shfl_xor_sync(0xffffffffu, s, o);
        q += __shfl_xor_sync(0xffffffffu, q, o);
    }
    const int lane = tid & 31, w = tid >> 5;
    if (lane == 0) { red[0][w] = s; red[1][w] = q; }
    __syncthreads();
    if (tid < 32) {
        s = (tid < 8) ? red[0][tid] : 0.f;
        q = (tid < 8) ? red[1][tid] : 0.f;
#pragma unroll
        for (int o = 4; o > 0; o >>= 1) {
            s += __shfl_xor_sync(0xffffffffu, s, o);
            q += __shfl_xor_sync(0xffffffffu, q, o);
        }
        if (tid == 0) {
            float mean = s * (1.f / BDIM);
            stats[0] = mean;
            stats[1] = rsqrtf(q * (1.f / BDIM) - mean * mean + 1e-5f);
        }
    }
    __syncthreads();
    const float mean = stats[0], rinv = stats[1];
    const float4 gg = ((const float4*)g)[tid];
    const float4 bb = ((const float4*)b)[tid];
    float4 o4;
    o4.x = (v.x - mean) * rinv * gg.x + bb.x;
    o4.y = (v.y - mean) * rinv * gg.y + bb.y;
    o4.z = (v.z - mean) * rinv * gg.z + bb.z;
    o4.w = (v.w - mean) * rinv * gg.w + bb.w;
    if (Y) ((float4*)(Y + (size_t)row * BDIM))[tid] = o4;
    if (Yh) {
        size_t base = (size_t)row * BDIM + tid * 4;
        *(__half2*)(Yh + base)     = __floats2half2_rn(o4.x, o4.y);
        *(__half2*)(Yh + base + 2) = __floats2half2_rn(o4.z, o4.w);
    }
}

// ======================= launcher =======================
extern "C" void kernel_launch(void* const* d_in, const int* in_sizes, int n_in,
                              void* d_out, int out_size)
{
    const float* x    = (const float*)d_in[0];
    const float* y    = (const float*)d_in[1];
    const int*   mask = (const int*)  d_in[2];
    const float* Wq = (const float*)d_in[3];  const float* bq = (const float*)d_in[4];
    const float* Wk = (const float*)d_in[5];  const float* bk = (const float*)d_in[6];
    const float* Wv = (const float*)d_in[7];  const float* bv = (const float*)d_in[8];
    const float* Wo = (const float*)d_in[9];  const float* bo = (const float*)d_in[10];
    const float* W1 = (const float*)d_in[11]; const float* b1 = (const float*)d_in[12];
    const float* W2 = (const float*)d_in[13]; const float* b2 = (const float*)d_in[14];
    const float* g1 = (const float*)d_in[15]; const float* be1 = (const float*)d_in[16];
    const float* g2 = (const float*)d_in[17]; const float* be2 = (const float*)d_in[18];
    float* out = (float*)d_out;

    float *s1p, *x1p, *s2p;
    fp16 *xh, *yh, *qh, *kh, *vh, *ah, *x1h, *hh;
    fp16 *wq, *wkv, *wo, *w1, *w2;
    cudaGetSymbolAddress((void**)&s1p, g_s1);  cudaGetSymbolAddress((void**)&x1p, g_x1);
    cudaGetSymbolAddress((void**)&s2p, g_s2);
    cudaGetSymbolAddress((void**)&xh, g_xh);   cudaGetSymbolAddress((void**)&yh, g_yh);
    cudaGetSymbolAddress((void**)&qh, g_Qh);   cudaGetSymbolAddress((void**)&kh, g_Kh);
    cudaGetSymbolAddress((void**)&vh, g_Vh);   cudaGetSymbolAddress((void**)&ah, g_ah);
    cudaGetSymbolAddress((void**)&x1h, g_x1h); cudaGetSymbolAddress((void**)&hh, g_hh);
    cudaGetSymbolAddress((void**)&wq, g_wqT);  cudaGetSymbolAddress((void**)&wkv, g_wkvT);
    cudaGetSymbolAddress((void**)&wo, g_woT);
    cudaGetSymbolAddress((void**)&w1, g_w1T);  cudaGetSymbolAddress((void**)&w2, g_w2T);

    cudaFuncSetAttribute(mma_gemm, cudaFuncAttributeMaxDynamicSharedMemorySize, GEMM_SMEM);
    cudaFuncSetAttribute(mma_qkv,  cudaFuncAttributeMaxDynamicSharedMemorySize, GEMM_SMEM);
    cudaFuncSetAttribute(attn_tc,  cudaFuncAttributeMaxDynamicSharedMemorySize, AT_SMEM);

    // ---- weight prep: single launch for all 6 transposes ----
    dim3 tb(32, 8);
    wtrans6_kernel<<<dim3(HIDN / 32, BDIM / 32, 6), tb>>>(
        Wq, Wk, Wv, Wo, W1, W2, wq, wkv, wo, w1, w2);

    // ---- activation fp16 conversion (x and y in one launch) ----
    cvt_h2<<<dim3((MROWS * BDIM) / 2048, 2), 256>>>(x, xh, y, yh);

    dim3 gD(BDIM / 128, MROWS / 128);          // 8 x 32
    dim3 gQKV(3 * BDIM / 128, MROWS / 128);    // 24 x 32 = 768 CTAs (fused Q+K+V)
    dim3 gH(HIDN / 128, MROWS / 128);          // 32 x 32

    // fused QKV projections -> [B,H,S,DK] fp16
    mma_qkv<<<gQKV, 256, GEMM_SMEM>>>(xh, yh, wq, wkv, bq, bk, bv, qh, kh, vh, BDIM);

    // tensor-core flash attention -> fp16 [B,S,D]
    attn_tc<<<dim3(SEQ / 128, NH, NB), 256, AT_SMEM>>>(qh, kh, vh, mask, ah);

    // s1 = x + attn @ Wo + bo ; x1 = LN(s1) (+fp16)
    mma_gemm<<<gD, 256, GEMM_SMEM>>>(ah, wo, bo, x, s1p, nullptr, MROWS, BDIM, BDIM, MODE_RES);
    ln_kernel<<<MROWS, 256>>>(s1p, g1, be1, x1p, x1h);

    // FFN
    mma_gemm<<<gH, 256, GEMM_SMEM>>>(x1h, w1, b1, nullptr, nullptr, hh, MROWS, HIDN, BDIM, MODE_RELU_H);
    mma_gemm<<<gD, 256, GEMM_SMEM>>>(hh, w2, b2, x1p, s2p, nullptr, MROWS, BDIM, HIDN, MODE_RES);
    ln_kernel<<<MROWS, 256>>>(s2p, g2, be2, out, nullptr);
}

// round 15
// speedup vs baseline: 1.1470x; 1.0112x over previous
#include <cuda_runtime.h>
#include <cuda_fp16.h>
#include <math.h>
#include <stdint.h>

#define BDIM 1024
#define SEQ  2048
#define NH   16
#define DKH  64
#define HIDN 4096
#define MROWS 4096   // B*S
#define NB   2

typedef __half fp16;

// ---------------- scratch (static device globals; no allocation) ----------------
__device__ float g_s1 [MROWS * BDIM];
__device__ float g_x1 [MROWS * BDIM];
__device__ float g_s2 [MROWS * BDIM];

__device__ fp16 g_xh  [MROWS * BDIM];
__device__ fp16 g_yh  [MROWS * BDIM];
__device__ fp16 g_Qh  [MROWS * BDIM];   // [B,H,S,DK] (pre-scaled by 0.125*log2e)
__device__ fp16 g_Kh  [MROWS * BDIM];
__device__ fp16 g_Vh  [MROWS * BDIM];
__device__ fp16 g_ah  [MROWS * BDIM];   // attention output [B,S,D]
__device__ fp16 g_x1h [MROWS * BDIM];
__device__ fp16 g_hh  [MROWS * HIDN];

// transposed weights: Wt[N][K] fp16
__device__ fp16 g_wqT [BDIM * BDIM];
__device__ fp16 g_wkvT[2 * BDIM * BDIM];   // [Wk^T ; Wv^T]
__device__ fp16 g_woT [BDIM * BDIM];
__device__ fp16 g_w1T [HIDN * BDIM];
__device__ fp16 g_w2T [BDIM * HIDN];

enum { MODE_RELU_H = 1, MODE_RES = 2 };

// ======================= PTX helpers =======================
__device__ __forceinline__ uint32_t smem_u32(const void* p) {
    uint32_t a;
    asm("{ .reg .u64 t; cvta.to.shared.u64 t, %1; cvt.u32.u64 %0, t; }" : "=r"(a) : "l"(p));
    return a;
}
__device__ __forceinline__ void cp16(uint32_t s, const void* g) {
    asm volatile("cp.async.cg.shared.global [%0], [%1], 16;" :: "r"(s), "l"(g));
}
#define CP_COMMIT() asm volatile("cp.async.commit_group;" ::: "memory")
#define CP_WAIT0()  asm volatile("cp.async.wait_group 0;" ::: "memory")
#define CP_WAIT1()  asm volatile("cp.async.wait_group 1;" ::: "memory")

__device__ __forceinline__ void ldm_x4(uint32_t& r0, uint32_t& r1, uint32_t& r2, uint32_t& r3, uint32_t a) {
    asm volatile("ldmatrix.sync.aligned.m8n8.x4.shared.b16 {%0,%1,%2,%3}, [%4];"
                 : "=r"(r0), "=r"(r1), "=r"(r2), "=r"(r3) : "r"(a));
}
__device__ __forceinline__ void ldm_x4_t(uint32_t& r0, uint32_t& r1, uint32_t& r2, uint32_t& r3, uint32_t a) {
    asm volatile("ldmatrix.sync.aligned.m8n8.x4.trans.shared.b16 {%0,%1,%2,%3}, [%4];"
                 : "=r"(r0), "=r"(r1), "=r"(r2), "=r"(r3) : "r"(a));
}
__device__ __forceinline__ void mma16816(float* c, const uint32_t* a, const uint32_t* b) {
    asm volatile("mma.sync.aligned.m16n8k16.row.col.f32.f16.f16.f32 "
                 "{%0,%1,%2,%3}, {%4,%5,%6,%7}, {%8,%9}, {%0,%1,%2,%3};"
                 : "+f"(c[0]), "+f"(c[1]), "+f"(c[2]), "+f"(c[3])
                 : "r"(a[0]), "r"(a[1]), "r"(a[2]), "r"(a[3]), "r"(b[0]), "r"(b[1]));
}
__device__ __forceinline__ uint32_t cvt2(float a, float b) {
    __half2 t = __floats2half2_rn(a, b);
    return *(uint32_t*)&t;
}
__device__ __forceinline__ float ex2f(float x) {
    float y;
    asm("ex2.approx.f32 %0, %1;" : "=f"(y) : "f"(x));
    return y;
}

// ======================= GEMM common: BK=64, 2-stage, 8 warps (64x32 warp tile) =======================
#define GSTR   144                      // bytes per smem row (64 fp16 + 8 pad)
#define TILE_B (128 * GSTR)             // 18432 B
#define SLAB_B (2 * TILE_B)             // 36864 B (A tile + B tile)
#define GEMM_SMEM (2 * SLAB_B)          // 73728 B (2 stages)

#define LOAD_SLAB(ST, KS) do {                                                \
        const uint32_t _sb = smb + (ST) * SLAB_B;                             \
        const int _ko = (KS) * 64;                                            \
        _Pragma("unroll")                                                     \
        for (int t = 0; t < 2; t++) {                                         \
            const fp16* g = src[t] + _ko;                                     \
            const uint32_t tb = _sb + t * TILE_B;                             \
            _Pragma("unroll")                                                 \
            for (int u = 0; u < 4; u++) {                                     \
                int p = tid + u * 256;                                        \
                int r = p >> 3, c = p & 7;                                    \
                cp16(tb + (uint32_t)(r * GSTR + c * 16),                      \
                     g + (size_t)r * K + c * 8);                              \
            }                                                                 \
        }                                                                     \
        CP_COMMIT();                                                          \
    } while (0)

#define GEMM_SLAB_MMA(ST) do {                                                \
        const uint32_t ab = smb + (ST) * SLAB_B;                              \
        const uint32_t bb = ab + TILE_B;                                      \
        _Pragma("unroll")                                                     \
        for (int kk = 0; kk < 4; kk++) {                                      \
            const uint32_t koff = kk * 32 + lcol16;                           \
            uint32_t af[4][4];                                                \
            _Pragma("unroll")                                                 \
            for (int mi = 0; mi < 4; mi++) {                                  \
                uint32_t ra = (uint32_t)((warp_m * 64 + mi * 16 + lrow) * GSTR) + koff; \
                ldm_x4(af[mi][0], af[mi][1], af[mi][2], af[mi][3], ab + ra);  \
            }                                                                 \
            uint32_t bf[4][2];                                                \
            _Pragma("unroll")                                                 \
            for (int nt = 0; nt < 2; nt++) {                                  \
                uint32_t rb = (uint32_t)((warp_n * 32 + nt * 16 + lrow) * GSTR) + koff; \
                uint32_t r0, r1, r2, r3;                                      \
                ldm_x4(r0, r1, r2, r3, bb + rb);                              \
                bf[nt * 2 + 0][0] = r0; bf[nt * 2 + 0][1] = r2;               \
                bf[nt * 2 + 1][0] = r1; bf[nt * 2 + 1][1] = r3;               \
            }                                                                 \
            _Pragma("unroll")                                                 \
            for (int mi = 0; mi < 4; mi++)                                    \
                _Pragma("unroll")                                             \
                for (int ni = 0; ni < 4; ni++)                                \
                    mma16816(acc[mi][ni], af[mi], bf[ni]);                    \
        }                                                                     \
    } while (0)

#define GEMM_PROLOG()                                                         \
    extern __shared__ char sm[];                                              \
    const uint32_t smb = smem_u32(sm);                                        \
    const int tid = threadIdx.x;                                              \
    const int wid = tid >> 5;                                                 \
    const int lid = tid & 31;                                                 \
    const int warp_m = wid >> 2;                                              \
    const int warp_n = wid & 3;                                               \
    const uint32_t lrow = (uint32_t)(lid & 15);                               \
    const uint32_t lcol16 = (uint32_t)(lid >> 4) * 16;                        \
    float acc[4][4][4];                                                       \
    _Pragma("unroll")                                                         \
    for (int i = 0; i < 4; i++)                                               \
        _Pragma("unroll")                                                     \
        for (int j = 0; j < 4; j++)                                           \
            _Pragma("unroll")                                                 \
            for (int f = 0; f < 4; f++) acc[i][j][f] = 0.f;

#define GEMM_MAINLOOP()                                                       \
    const int NS = K / 64;                                                    \
    LOAD_SLAB(0, 0);                                                          \
    int st = 0;                                                               \
    for (int s = 0; s < NS; s++) {                                            \
        if (s + 1 < NS) { LOAD_SLAB(st ^ 1, s + 1); CP_WAIT1(); }             \
        else            { CP_WAIT0(); }                                       \
        __syncthreads();                                                      \
        GEMM_SLAB_MMA(st);                                                    \
        __syncthreads();                                                      \
        st ^= 1;                                                              \
    }

// ======================= generic GEMM (Wo / W1 / W2 paths) =======================
__global__ __launch_bounds__(256, 2) void mma_gemm(
    const fp16* __restrict__ A, const fp16* __restrict__ B,
    const float* __restrict__ bias, const float* __restrict__ R,
    float* __restrict__ outF, fp16* __restrict__ outH,
    int M, int N, int K, int mode)
{
    GEMM_PROLOG();
    const int row0 = blockIdx.y * 128;
    const int col0 = blockIdx.x * 128;
    const fp16* src[2];
    src[0] = A + (size_t)row0 * K;
    src[1] = B + (size_t)col0 * K;
    GEMM_MAINLOOP();

    const int qr = lid >> 2;
    const int qc = (lid & 3) * 2;
#pragma unroll
    for (int mi = 0; mi < 4; mi++) {
#pragma unroll
        for (int ni = 0; ni < 4; ni++) {
            const int n = col0 + warp_n * 32 + ni * 8 + qc;
            const float b0 = bias[n], b1 = bias[n + 1];
#pragma unroll
            for (int half = 0; half < 2; half++) {
                const int m = row0 + warp_m * 64 + mi * 16 + qr + half * 8;
                float v0 = acc[mi][ni][half * 2 + 0] + b0;
                float v1 = acc[mi][ni][half * 2 + 1] + b1;
                if (mode == MODE_RES) {
                    const float* rp = &R[(size_t)m * N + n];
                    v0 += rp[0]; v1 += rp[1];
                    float2 o2 = {v0, v1};
                    *(float2*)&outF[(size_t)m * N + n] = o2;
                } else { // MODE_RELU_H
                    v0 = fmaxf(v0, 0.f); v1 = fmaxf(v1, 0.f);
                    *(__half2*)&outH[(size_t)m * N + n] = __floats2half2_rn(v0, v1);
                }
            }
        }
    }
}

// ======================= fused QKV GEMM (Q pre-scaled by 0.125*log2e) =======================
__global__ __launch_bounds__(256, 2) void mma_qkv(
    const fp16* __restrict__ Aq, const fp16* __restrict__ Akv,
    const fp16* __restrict__ Bq, const fp16* __restrict__ Bkv,
    const float* __restrict__ bq, const float* __restrict__ bk, const float* __restrict__ bv,
    fp16* __restrict__ qh, fp16* __restrict__ kh, fp16* __restrict__ vh,
    int K)
{
    GEMM_PROLOG();
    const bool isQ = (blockIdx.x < 8);
    const int row0 = blockIdx.y * 128;
    const int col0 = (isQ ? blockIdx.x : (blockIdx.x - 8)) * 128;
    const fp16* src[2];
    src[0] = (isQ ? Aq : Akv) + (size_t)row0 * K;
    src[1] = (isQ ? Bq : Bkv) + (size_t)col0 * K;
    GEMM_MAINLOOP();

    const float oscl = isQ ? (0.125f * 1.44269504f) : 1.0f;
    const int qr = lid >> 2;
    const int qc = (lid & 3) * 2;
#pragma unroll
    for (int mi = 0; mi < 4; mi++) {
#pragma unroll
        for (int ni = 0; ni < 4; ni++) {
            const int n = col0 + warp_n * 32 + ni * 8 + qc;
            fp16* dst; const float* bp; int nn;
            if (isQ)           { dst = qh; bp = bq; nn = n; }
            else if (n < BDIM) { dst = kh; bp = bk; nn = n; }
            else               { dst = vh; bp = bv; nn = n - BDIM; }
            const float b0 = bp[nn], b1 = bp[nn + 1];
#pragma unroll
            for (int half = 0; half < 2; half++) {
                const int m = row0 + warp_m * 64 + mi * 16 + qr + half * 8;
                float v0 = (acc[mi][ni][half * 2 + 0] + b0) * oscl;
                float v1 = (acc[mi][ni][half * 2 + 1] + b1) * oscl;
                int hh = nn >> 6, dk = nn & 63, bb = m >> 11, ss = m & 2047;
                size_t o = (((size_t)(bb * NH + hh)) * SEQ + ss) * DKH + dk;
                *(__half2*)&dst[o] = __floats2half2_rn(v0, v1);
            }
        }
    }
}

// ======================= tensor-core flash attention (fp16, KV tile 128) =======================
#define AT_STRIDE 144
#define AT_KTILE  (128 * AT_STRIDE)           // 18432 B per 128x64 fp16 tile
#define AT_STAGE  (2 * AT_KTILE)              // K + V = 36864
#define AT_MSKOFF (2 * AT_STAGE)              // 73728
#define AT_SMEM   (AT_MSKOFF + 2 * 512 + 128)

__global__ __launch_bounds__(256, 2) void attn_tc(
    const fp16* __restrict__ Qg, const fp16* __restrict__ Kg,
    const fp16* __restrict__ Vg, const int* __restrict__ mask,
    fp16* __restrict__ O_out)
{
    extern __shared__ char sm[];
    const uint32_t smb = smem_u32(sm);
    const int tid = threadIdx.x;
    const int wid = tid >> 5;
    const int lid = tid & 31;
    const int q0  = blockIdx.x * 128;
    const int h   = blockIdx.y;
    const int bz  = blockIdx.z;
    const size_t hoff = ((size_t)(bz * NH + h)) * SEQ * DKH;

    const uint32_t lr   = (uint32_t)(lid & 15);
    const uint32_t lc16 = (uint32_t)(lid >> 4) * 16;

    // ---- Q tile -> smem (stage-0 K region, consumed before KV loads), then frags ----
    {
        const fp16* qh = Qg + hoff + (size_t)q0 * DKH;
#pragma unroll
        for (int u = 0; u < 4; u++) {
            int p = tid + u * 256;
            int r = p >> 3, c = p & 7;
            cp16(smb + (uint32_t)(r * AT_STRIDE + c * 16), qh + (size_t)r * DKH + c * 8);
        }
        CP_COMMIT(); CP_WAIT0();
    }
    __syncthreads();
    uint32_t qf[4][4];
#pragma unroll
    for (int ks = 0; ks < 4; ks++) {
        uint32_t ra = (uint32_t)((wid * 16 + lr) * AT_STRIDE) + ks * 32 + lc16;
        ldm_x4(qf[ks][0], qf[ks][1], qf[ks][2], qf[ks][3], smb + ra);
    }
    __syncthreads();

    float O[8][4];
#pragma unroll
    for (int i = 0; i < 8; i++)
#pragma unroll
        for (int j = 0; j < 4; j++) O[i][j] = 0.f;
    float m0 = -INFINITY, m1 = -INFINITY, l0 = 0.f, l1 = 0.f;

    const fp16* kg = Kg + hoff;
    const fp16* vg = Vg + hoff;
    const int*  mkg = mask + bz * SEQ;

#define LOAD_KV(ST, T) do {                                                     \
        const uint32_t _sb = smb + (ST) * AT_STAGE;                             \
        const int _k0 = (T) * 128;                                              \
        _Pragma("unroll")                                                       \
        for (int u = 0; u < 4; u++) {                                           \
            int p = tid + u * 256;                                              \
            int r = p >> 3, c = p & 7;                                          \
            uint32_t so = (uint32_t)(r * AT_STRIDE + c * 16);                   \
            size_t go = (size_t)(_k0 + r) * DKH + c * 8;                        \
            cp16(_sb + so, kg + go);                                            \
            cp16(_sb + AT_KTILE + so, vg + go);                                 \
        }                                                                       \
        if (tid < 32) cp16(smb + AT_MSKOFF + (ST) * 512 + tid * 16, mkg + _k0 + tid * 4); \
        CP_COMMIT();                                                            \
    } while (0)

    LOAD_KV(0, 0);

    for (int t = 0; t < SEQ / 128; t++) {
        const int st = t & 1;
        if (t + 1 < SEQ / 128) { LOAD_KV(st ^ 1, t + 1); CP_WAIT1(); }
        else                   { CP_WAIT0(); }

        const uint32_t kb = smb + st * AT_STAGE;
        const uint32_t vb = kb + AT_KTILE;
        const int* msk = (const int*)(sm + AT_MSKOFF + st * 512);

        // barrier doubles as all-unmasked vote for this 128-wide KV tile
        const int allv = __syncthreads_and((int)(msk[tid & 127] != 0));

#pragma unroll
        for (int hf = 0; hf < 2; hf++) {
            const int kr0 = hf * 64;

            // ---- scores: QK^T on 64 KV columns (already in log2 domain) ----
            float s[8][4];
#pragma unroll
            for (int i = 0; i < 8; i++)
#pragma unroll
                for (int j = 0; j < 4; j++) s[i][j] = 0.f;

#pragma unroll
            for (int ks = 0; ks < 4; ks++) {
                const uint32_t koff = ks * 32 + lc16;
#pragma unroll
                for (int g = 0; g < 4; g++) {
                    uint32_t rb = (uint32_t)((kr0 + g * 16 + lr) * AT_STRIDE) + koff;
                    uint32_t r0, r1, r2, r3;
                    ldm_x4(r0, r1, r2, r3, kb + rb);
                    uint32_t b0[2] = {r0, r2}, b1[2] = {r1, r3};
                    mma16816(s[2 * g],     qf[ks], b0);
                    mma16816(s[2 * g + 1], qf[ks], b1);
                }
            }

            // ---- mask (slow path only when some position is masked) ----
            if (!allv) {
#pragma unroll
                for (int j = 0; j < 8; j++) {
                    int c0 = kr0 + j * 8 + (lid & 3) * 2;
                    bool z0 = (msk[c0] == 0), z1 = (msk[c0 + 1] == 0);
                    if (z0) { s[j][0] = -1e9f; s[j][2] = -1e9f; }
                    if (z1) { s[j][1] = -1e9f; s[j][3] = -1e9f; }
                }
            }

            // ---- online softmax (rows r and r+8), exp2 domain ----
            float mx0 = -INFINITY, mx1 = -INFINITY;
#pragma unroll
            for (int j = 0; j < 8; j++) {
                mx0 = fmaxf(mx0, fmaxf(s[j][0], s[j][1]));
                mx1 = fmaxf(mx1, fmaxf(s[j][2], s[j][3]));
            }
#pragma unroll
            for (int off = 1; off <= 2; off <<= 1) {
                mx0 = fmaxf(mx0, __shfl_xor_sync(0xffffffffu, mx0, off));
                mx1 = fmaxf(mx1, __shfl_xor_sync(0xffffffffu, mx1, off));
            }
            float nm0 = fmaxf(m0, mx0), nm1 = fmaxf(m1, mx1);
            float sum0 = 0.f, sum1 = 0.f;
#pragma unroll
            for (int j = 0; j < 8; j++) {
                s[j][0] = ex2f(s[j][0] - nm0); sum0 += s[j][0];
                s[j][1] = ex2f(s[j][1] - nm0); sum0 += s[j][1];
                s[j][2] = ex2f(s[j][2] - nm1); sum1 += s[j][2];
                s[j][3] = ex2f(s[j][3] - nm1); sum1 += s[j][3];
            }
#pragma unroll
            for (int off = 1; off <= 2; off <<= 1) {
                sum0 += __shfl_xor_sync(0xffffffffu, sum0, off);
                sum1 += __shfl_xor_sync(0xffffffffu, sum1, off);
            }
            const bool same = (nm0 == m0) && (nm1 == m1);
            if (__all_sync(0xffffffffu, same)) {
                l0 += sum0; l1 += sum1;
            } else {
                float a0 = ex2f(m0 - nm0), a1 = ex2f(m1 - nm1);
                l0 = l0 * a0 + sum0;
                l1 = l1 * a1 + sum1;
                m0 = nm0; m1 = nm1;
#pragma unroll
                for (int i = 0; i < 8; i++) {
                    O[i][0] *= a0; O[i][1] *= a0;
                    O[i][2] *= a1; O[i][3] *= a1;
                }
            }

            // ---- O += P @ V ----
#pragma unroll
            for (int j = 0; j < 4; j++) {
                uint32_t P[4];
                P[0] = cvt2(s[2 * j][0],     s[2 * j][1]);
                P[1] = cvt2(s[2 * j][2],     s[2 * j][3]);
                P[2] = cvt2(s[2 * j + 1][0], s[2 * j + 1][1]);
                P[3] = cvt2(s[2 * j + 1][2], s[2 * j + 1][3]);
#pragma unroll
                for (int c = 0; c < 4; c++) {
                    uint32_t r0, r1, r2, r3;
                    ldm_x4_t(r0, r1, r2, r3,
                             vb + (uint32_t)((kr0 + j * 16 + lr) * AT_STRIDE) + c * 32 + lc16);
                    uint32_t B0[2] = {r0, r1}, B1[2] = {r2, r3};
                    mma16816(O[2 * c],     P, B0);
                    mma16816(O[2 * c + 1], P, B1);
                }
            }
        }
        __syncthreads();
    }

    const float il0 = 1.f / (l0 > 0.f ? l0 : 1.f);
    const float il1 = 1.f / (l1 > 0.f ? l1 : 1.f);
    const int qr  = q0 + wid * 16 + (lid >> 2);
    const int col0 = h * DKH + (lid & 3) * 2;
#pragma unroll
    for (int nt = 0; nt < 8; nt++) {
        const int col = col0 + nt * 8;
        {
            __half2 p = __floats2half2_rn(O[nt][0] * il0, O[nt][1] * il0);
            *(__half2*)&O_out[((size_t)bz * SEQ + qr) * BDIM + col] = p;
        }
        {
            __half2 p = __floats2half2_rn(O[nt][2] * il1, O[nt][3] * il1);
            *(__half2*)&O_out[((size_t)bz * SEQ + qr + 8) * BDIM + col] = p;
        }
    }
}

// ======================= unified prep: 6 weight transposes + 2 activation converts =======================
// z 0..3: D x D (Wq, Wk, Wv, Wo) — uses only blockIdx.x < 32.
// z = 4: W1 [1024,4096] -> [4096,1024]; z = 5: W2 [4096,1024] -> [1024,4096].
// z = 6: cvt x -> xh; z = 7: cvt y -> yh (4 fp32 elems/thread).
__global__ __launch_bounds__(256) void prep_kernel(
    const float* __restrict__ Wq, const float* __restrict__ Wk,
    const float* __restrict__ Wv, const float* __restrict__ Wo,
    const float* __restrict__ W1g, const float* __restrict__ W2g,
    const float* __restrict__ Xg, const float* __restrict__ Yg,
    fp16* __restrict__ Tq, fp16* __restrict__ Tkv, fp16* __restrict__ To,
    fp16* __restrict__ T1, fp16* __restrict__ T2,
    fp16* __restrict__ HX, fp16* __restrict__ HY)
{
    __shared__ float t[32][33];
    const int z = blockIdx.z;
    const int tid = threadIdx.x;

    if (z >= 6) {
        const float* S = (z == 6) ? Xg : Yg;
        fp16* Dd = (z == 6) ? HX : HY;
        const int i = ((blockIdx.y * 128 + blockIdx.x) * 256 + tid) * 4;
        const float4 v = *(const float4*)(S + i);
        *(__half2*)(Dd + i)     = __floats2half2_rn(v.x, v.y);
        *(__half2*)(Dd + i + 2) = __floats2half2_rn(v.z, v.w);
        return;
    }

    const float* W; fp16* T; int K, N, n0, k0;
    if (z < 4) {
        if (blockIdx.x >= 32) return;
        W = (z == 0) ? Wq : (z == 1) ? Wk : (z == 2) ? Wv : Wo;
        T = (z == 0) ? Tq : (z == 1) ? Tkv : (z == 2) ? (Tkv + (size_t)BDIM * BDIM) : To;
        K = BDIM; N = BDIM;
        n0 = blockIdx.x * 32; k0 = blockIdx.y * 32;
    } else if (z == 4) {
        W = W1g; T = T1; K = BDIM; N = HIDN;
        n0 = blockIdx.x * 32; k0 = blockIdx.y * 32;
    } else {
        W = W2g; T = T2; K = HIDN; N = BDIM;
        n0 = blockIdx.y * 32; k0 = blockIdx.x * 32;
    }
    const int tx = tid & 31, ty = tid >> 5;
#pragma unroll
    for (int j = 0; j < 4; j++)
        t[ty + j * 8][tx] = W[(size_t)(k0 + ty + j * 8) * N + n0 + tx];
    __syncthreads();
#pragma unroll
    for (int j = 0; j < 4; j++)
        T[(size_t)(n0 + ty + j * 8) * K + k0 + tx] = __float2half(t[tx][ty + j * 8]);
}

// ======================= LayerNorm (+ optional fp16 output) =======================
__global__ __launch_bounds__(256) void ln_kernel(
    const float* __restrict__ X, const float* __restrict__ g,
    const float* __restrict__ b, float* __restrict__ Y, fp16* __restrict__ Yh)
{
    __shared__ float red[2][8];
    __shared__ float stats[2];
    const int row = blockIdx.x;
    const int tid = threadIdx.x;

    const float4 v = ((const float4*)(X + (size_t)row * BDIM))[tid];
    float s = v.x + v.y + v.z + v.w;
    float q = v.x * v.x + v.y * v.y + v.z * v.z + v.w * v.w;
#pragma unroll
    for (int o = 16; o > 0; o >>= 1) {
        s += __shfl_xor_sync(0xffffffffu, s, o);
        q += __shfl_xor_sync(0xffffffffu, q, o);
    }
    const int lane = tid & 31, w = tid >> 5;
    if (lane == 0) { red[0][w] = s; red[1][w] = q; }
    __syncthreads();
    if (tid < 32) {
        s = (tid < 8) ? red[0][tid] : 0.f;
        q = (tid < 8) ? red[1][tid] : 0.f;
#pragma unroll
        for (int o = 4; o > 0; o >>= 1) {
            s += __shfl_xor_sync(0xffffffffu, s, o);
            q += __shfl_xor_sync(0xffffffffu, q, o);
        }
        if (tid == 0) {
            float mean = s * (1.f / BDIM);
            stats[0] = mean;
            stats[1] = rsqrtf(q * (1.f / BDIM) - mean * mean + 1e-5f);
        }
    }
    __syncthreads();
    const float mean = stats[0], rinv = stats[1];
    const float4 gg = ((const float4*)g)[tid];
    const float4 bb = ((const float4*)b)[tid];
    float4 o4;
    o4.x = (v.x - mean) * rinv * gg.x + bb.x;
    o4.y = (v.y - mean) * rinv * gg.y + bb.y;
    o4.z = (v.z - mean) * rinv * gg.z + bb.z;
    o4.w = (v.w - mean) * rinv * gg.w + bb.w;
    if (Y) ((float4*)(Y + (size_t)row * BDIM))[tid] = o4;
    if (Yh) {
        size_t base = (size_t)row * BDIM + tid * 4;
        *(__half2*)(Yh + base)     = __floats2half2_rn(o4.x, o4.y);
        *(__half2*)(Yh + base + 2) = __floats2half2_rn(o4.z, o4.w);
    }
}

// ======================= launcher =======================
extern "C" void kernel_launch(void* const* d_in, const int* in_sizes, int n_in,
                              void* d_out, int out_size)
{
    const float* x    = (const float*)d_in[0];
    const float* y    = (const float*)d_in[1];
    const int*   mask = (const int*)  d_in[2];
    const float* Wq = (const float*)d_in[3];  const float* bq = (const float*)d_in[4];
    const float* Wk = (const float*)d_in[5];  const float* bk = (const float*)d_in[6];
    const float* Wv = (const float*)d_in[7];  const float* bv = (const float*)d_in[8];
    const float* Wo = (const float*)d_in[9];  const float* bo = (const float*)d_in[10];
    const float* W1 = (const float*)d_in[11]; const float* b1 = (const float*)d_in[12];
    const float* W2 = (const float*)d_in[13]; const float* b2 = (const float*)d_in[14];
    const float* g1 = (const float*)d_in[15]; const float* be1 = (const float*)d_in[16];
    const float* g2 = (const float*)d_in[17]; const float* be2 = (const float*)d_in[18];
    float* out = (float*)d_out;

    float *s1p, *x1p, *s2p;
    fp16 *xh, *yh, *qh, *kh, *vh, *ah, *x1h, *hh;
    fp16 *wq, *wkv, *wo, *w1, *w2;
    cudaGetSymbolAddress((void**)&s1p, g_s1);  cudaGetSymbolAddress((void**)&x1p, g_x1);
    cudaGetSymbolAddress((void**)&s2p, g_s2);
    cudaGetSymbolAddress((void**)&xh, g_xh);   cudaGetSymbolAddress((void**)&yh, g_yh);
    cudaGetSymbolAddress((void**)&qh, g_Qh);   cudaGetSymbolAddress((void**)&kh, g_Kh);
    cudaGetSymbolAddress((void**)&vh, g_Vh);   cudaGetSymbolAddress((void**)&ah, g_ah);
    cudaGetSymbolAddress((void**)&x1h, g_x1h); cudaGetSymbolAddress((void**)&hh, g_hh);
    cudaGetSymbolAddress((void**)&wq, g_wqT);  cudaGetSymbolAddress((void**)&wkv, g_wkvT);
    cudaGetSymbolAddress((void**)&wo, g_woT);
    cudaGetSymbolAddress((void**)&w1, g_w1T);  cudaGetSymbolAddress((void**)&w2, g_w2T);

    cudaFuncSetAttribute(mma_gemm, cudaFuncAttributeMaxDynamicSharedMemorySize, GEMM_SMEM);
    cudaFuncSetAttribute(mma_qkv,  cudaFuncAttributeMaxDynamicSharedMemorySize, GEMM_SMEM);
    cudaFuncSetAttribute(attn_tc,  cudaFuncAttributeMaxDynamicSharedMemorySize, AT_SMEM);

    // ---- prep: all 6 transposes + both activation converts in ONE launch ----
    prep_kernel<<<dim3(HIDN / 32, BDIM / 32, 8), 256>>>(
        Wq, Wk, Wv, Wo, W1, W2, x, y, wq, wkv, wo, w1, w2, xh, yh);

    dim3 gD(BDIM / 128, MROWS / 128);          // 8 x 32
    dim3 gQKV(3 * BDIM / 128, MROWS / 128);    // 24 x 32 = 768 CTAs (fused Q+K+V)
    dim3 gH(HIDN / 128, MROWS / 128);          // 32 x 32

    // fused QKV projections -> [B,H,S,DK] fp16 (Q pre-scaled into log2 domain)
    mma_qkv<<<gQKV, 256, GEMM_SMEM>>>(xh, yh, wq, wkv, bq, bk, bv, qh, kh, vh, BDIM);

    // tensor-core flash attention -> fp16 [B,S,D]
    attn_tc<<<dim3(SEQ / 128, NH, NB), 256, AT_SMEM>>>(qh, kh, vh, mask, ah);

    // s1 = x + attn @ Wo + bo ; x1 = LN(s1) (+fp16)
    mma_gemm<<<gD, 256, GEMM_SMEM>>>(ah, wo, bo, x, s1p, nullptr, MROWS, BDIM, BDIM, MODE_RES);
    ln_kernel<<<MROWS, 256>>>(s1p, g1, be1, x1p, x1h);

    // FFN
    mma_gemm<<<gH, 256, GEMM_SMEM>>>(x1h, w1, b1, nullptr, nullptr, hh, MROWS, HIDN, BDIM, MODE_RELU_H);
    mma_gemm<<<gD, 256, GEMM_SMEM>>>(hh, w2, b2, x1p, s2p, nullptr, MROWS, BDIM, HIDN, MODE_RES);
    ln_kernel<<<MROWS, 256>>>(s2p, g2, be2, out, nullptr);
}

// round 17
// speedup vs baseline: 1.1786x; 1.0275x over previous
#include <cuda_runtime.h>
#include <cuda_fp16.h>
#include <math.h>
#include <string.h>
#include <stdint.h>

#define BDIM 1024
#define SEQ  2048
#define NH   16
#define DKH  64
#define HIDN 4096
#define MROWS 4096   // B*S
#define NB   2

typedef __half fp16;

// ---------------- scratch (static device globals; no allocation) ----------------
__device__ float g_s1 [MROWS * BDIM];
__device__ float g_x1 [MROWS * BDIM];
__device__ float g_s2 [MROWS * BDIM];

__device__ fp16 g_xh  [MROWS * BDIM];
__device__ fp16 g_yh  [MROWS * BDIM];
__device__ fp16 g_Qh  [MROWS * BDIM];   // [B,H,S,DK] (pre-scaled by 0.125*log2e)
__device__ fp16 g_Kh  [MROWS * BDIM];
__device__ fp16 g_Vh  [MROWS * BDIM];
__device__ fp16 g_ah  [MROWS * BDIM];   // attention output [B,S,D]
__device__ fp16 g_x1h [MROWS * BDIM];
__device__ fp16 g_hh  [MROWS * HIDN];

// transposed weights: Wt[N][K] fp16
__device__ fp16 g_wqT [BDIM * BDIM];
__device__ fp16 g_wkvT[2 * BDIM * BDIM];   // [Wk^T ; Wv^T]
__device__ fp16 g_woT [BDIM * BDIM];
__device__ fp16 g_w1T [HIDN * BDIM];
__device__ fp16 g_w2T [BDIM * HIDN];

enum { MODE_RELU_H = 1, MODE_RES = 2 };

// ======================= PTX helpers =======================
__device__ __forceinline__ uint32_t smem_u32(const void* p) {
    uint32_t a;
    asm("{ .reg .u64 t; cvta.to.shared.u64 t, %1; cvt.u32.u64 %0, t; }" : "=r"(a) : "l"(p));
    return a;
}
__device__ __forceinline__ void cp16(uint32_t s, const void* g) {
    asm volatile("cp.async.cg.shared.global [%0], [%1], 16;" :: "r"(s), "l"(g));
}
#define CP_COMMIT() asm volatile("cp.async.commit_group;" ::: "memory")
#define CP_WAIT0()  asm volatile("cp.async.wait_group 0;" ::: "memory")
#define CP_WAIT1()  asm volatile("cp.async.wait_group 1;" ::: "memory")

#define PDL_WAIT()  asm volatile("griddepcontrol.wait;" ::: "memory")

__device__ __forceinline__ void ldm_x4(uint32_t& r0, uint32_t& r1, uint32_t& r2, uint32_t& r3, uint32_t a) {
    asm volatile("ldmatrix.sync.aligned.m8n8.x4.shared.b16 {%0,%1,%2,%3}, [%4];"
                 : "=r"(r0), "=r"(r1), "=r"(r2), "=r"(r3) : "r"(a));
}
__device__ __forceinline__ void ldm_x4_t(uint32_t& r0, uint32_t& r1, uint32_t& r2, uint32_t& r3, uint32_t a) {
    asm volatile("ldmatrix.sync.aligned.m8n8.x4.trans.shared.b16 {%0,%1,%2,%3}, [%4];"
                 : "=r"(r0), "=r"(r1), "=r"(r2), "=r"(r3) : "r"(a));
}
__device__ __forceinline__ void mma16816(float* c, const uint32_t* a, const uint32_t* b) {
    asm volatile("mma.sync.aligned.m16n8k16.row.col.f32.f16.f16.f32 "
                 "{%0,%1,%2,%3}, {%4,%5,%6,%7}, {%8,%9}, {%0,%1,%2,%3};"
                 : "+f"(c[0]), "+f"(c[1]), "+f"(c[2]), "+f"(c[3])
                 : "r"(a[0]), "r"(a[1]), "r"(a[2]), "r"(a[3]), "r"(b[0]), "r"(b[1]));
}
__device__ __forceinline__ uint32_t cvt2(float a, float b) {
    __half2 t = __floats2half2_rn(a, b);
    return *(uint32_t*)&t;
}
__device__ __forceinline__ uint32_t ex2_h2(uint32_t x) {
    uint32_t y;
    asm("ex2.approx.f16x2 %0, %1;" : "=r"(y) : "r"(x));
    return y;
}
__device__ __forceinline__ float ex2f(float x) {
    float y;
    asm("ex2.approx.f32 %0, %1;" : "=f"(y) : "f"(x));
    return y;
}

// ======================= GEMM common: BK=64, 2-stage, 8 warps (64x32 warp tile) =======================
#define GSTR   144                      // bytes per smem row (64 fp16 + 8 pad)
#define TILE_B (128 * GSTR)             // 18432 B
#define SLAB_B (2 * TILE_B)             // 36864 B (A tile + B tile)
#define GEMM_SMEM (2 * SLAB_B)          // 73728 B (2 stages)

#define LOAD_SLAB(ST, KS) do {                                                \
        const uint32_t _sb = smb + (ST) * SLAB_B;                             \
        const int _ko = (KS) * 64;                                            \
        _Pragma("unroll")                                                     \
        for (int t = 0; t < 2; t++) {                                         \
            const fp16* g = src[t] + _ko;                                     \
            const uint32_t tb = _sb + t * TILE_B;                             \
            _Pragma("unroll")                                                 \
            for (int u = 0; u < 4; u++) {                                     \
                int p = tid + u * 256;                                        \
                int r = p >> 3, c = p & 7;                                    \
                cp16(tb + (uint32_t)(r * GSTR + c * 16),                      \
                     g + (size_t)r * K + c * 8);                              \
            }                                                                 \
        }                                                                     \
        CP_COMMIT();                                                          \
    } while (0)

// single-operand tile load (T=0: A tile, T=1: B tile) into stage ST, slab KS
#define LOAD_T_ONLY(T, ST, KS) do {                                           \
        const uint32_t _sb = smb + (ST) * SLAB_B;                             \
        const int _ko = (KS) * 64;                                            \
        const fp16* g = src[T] + _ko;                                         \
        const uint32_t tb = _sb + (T) * TILE_B;                               \
        _Pragma("unroll")                                                     \
        for (int u = 0; u < 4; u++) {                                         \
            int p = tid + u * 256;                                            \
            int r = p >> 3, c = p & 7;                                        \
            cp16(tb + (uint32_t)(r * GSTR + c * 16),                          \
                 g + (size_t)r * K + c * 8);                                  \
        }                                                                     \
        CP_COMMIT();                                                          \
    } while (0)

#define GEMM_SLAB_MMA(ST) do {                                                \
        const uint32_t ab = smb + (ST) * SLAB_B;                              \
        const uint32_t bb = ab + TILE_B;                                      \
        _Pragma("unroll")                                                     \
        for (int kk = 0; kk < 4; kk++) {                                      \
            const uint32_t koff = kk * 32 + lcol16;                           \
            uint32_t af[4][4];                                                \
            _Pragma("unroll")                                                 \
            for (int mi = 0; mi < 4; mi++) {                                  \
                uint32_t ra = (uint32_t)((warp_m * 64 + mi * 16 + lrow) * GSTR) + koff; \
                ldm_x4(af[mi][0], af[mi][1], af[mi][2], af[mi][3], ab + ra);  \
            }                                                                 \
            uint32_t bf[4][2];                                                \
            _Pragma("unroll")                                                 \
            for (int nt = 0; nt < 2; nt++) {                                  \
                uint32_t rb = (uint32_t)((warp_n * 32 + nt * 16 + lrow) * GSTR) + koff; \
                uint32_t r0, r1, r2, r3;                                      \
                ldm_x4(r0, r1, r2, r3, bb + rb);                              \
                bf[nt * 2 + 0][0] = r0; bf[nt * 2 + 0][1] = r2;               \
                bf[nt * 2 + 1][0] = r1; bf[nt * 2 + 1][1] = r3;               \
            }                                                                 \
            _Pragma("unroll")                                                 \
            for (int mi = 0; mi < 4; mi++)                                    \
                _Pragma("unroll")                                             \
                for (int ni = 0; ni < 4; ni++)                                \
                    mma16816(acc[mi][ni], af[mi], bf[ni]);                    \
        }                                                                     \
    } while (0)

#define GEMM_PROLOG()                                                         \
    extern __shared__ char sm[];                                              \
    const uint32_t smb = smem_u32(sm);                                        \
    const int tid = threadIdx.x;                                              \
    const int wid = tid >> 5;                                                 \
    const int lid = tid & 31;                                                 \
    const int warp_m = wid >> 2;                                              \
    const int warp_n = wid & 3;                                               \
    const uint32_t lrow = (uint32_t)(lid & 15);                               \
    const uint32_t lcol16 = (uint32_t)(lid >> 4) * 16;                        \
    float acc[4][4][4];                                                       \
    _Pragma("unroll")                                                         \
    for (int i = 0; i < 4; i++)                                               \
        _Pragma("unroll")                                                     \
        for (int j = 0; j < 4; j++)                                           \
            _Pragma("unroll")                                                 \
            for (int f = 0; f < 4; f++) acc[i][j][f] = 0.f;

#define GEMM_LOOP_BODY()                                                      \
    int st = 0;                                                               \
    for (int s = 0; s < NS; s++) {                                            \
        if (s + 1 < NS) { LOAD_SLAB(st ^ 1, s + 1); CP_WAIT1(); }             \
        else            { CP_WAIT0(); }                                       \
        __syncthreads();                                                      \
        GEMM_SLAB_MMA(st);                                                    \
        __syncthreads();                                                      \
        st ^= 1;                                                              \
    }

// ======================= generic GEMM (Wo / W1 / W2 paths) =======================
// PDL: weight (B) tile of slab 0 is prefetched BEFORE the dependency wait.
__global__ __launch_bounds__(256, 2) void mma_gemm(
    const fp16* __restrict__ A, const fp16* __restrict__ B,
    const float* __restrict__ bias, const float* __restrict__ R,
    float* __restrict__ outF, fp16* __restrict__ outH,
    int M, int N, int K, int mode)
{
    GEMM_PROLOG();
    const int row0 = blockIdx.y * 128;
    const int col0 = blockIdx.x * 128;
    const fp16* src[2];
    src[0] = A + (size_t)row0 * K;
    src[1] = B + (size_t)col0 * K;
    const int NS = K / 64;

    LOAD_T_ONLY(1, 0, 0);   // weights: independent of immediate upstream
    PDL_WAIT();
    LOAD_T_ONLY(0, 0, 0);   // activations: depend on upstream

    GEMM_LOOP_BODY();

    const int qr = lid >> 2;
    const int qc = (lid & 3) * 2;
#pragma unroll
    for (int mi = 0; mi < 4; mi++) {
#pragma unroll
        for (int ni = 0; ni < 4; ni++) {
            const int n = col0 + warp_n * 32 + ni * 8 + qc;
            const float b0 = bias[n], b1 = bias[n + 1];
#pragma unroll
            for (int half = 0; half < 2; half++) {
                const int m = row0 + warp_m * 64 + mi * 16 + qr + half * 8;
                float v0 = acc[mi][ni][half * 2 + 0] + b0;
                float v1 = acc[mi][ni][half * 2 + 1] + b1;
                if (mode == MODE_RES) {
                    const float* rp = &R[(size_t)m * N + n];
                    v0 += rp[0]; v1 += rp[1];
                    float2 o2 = {v0, v1};
                    *(float2*)&outF[(size_t)m * N + n] = o2;
                } else { // MODE_RELU_H
                    v0 = fmaxf(v0, 0.f); v1 = fmaxf(v1, 0.f);
                    *(__half2*)&outH[(size_t)m * N + n] = __floats2half2_rn(v0, v1);
                }
            }
        }
    }
}

// ======================= fused QKV GEMM (Q pre-scaled by 0.125*log2e) =======================
__global__ __launch_bounds__(256, 2) void mma_qkv(
    const fp16* __restrict__ Aq, const fp16* __restrict__ Akv,
    const fp16* __restrict__ Bq, const fp16* __restrict__ Bkv,
    const float* __restrict__ bq, const float* __restrict__ bk, const float* __restrict__ bv,
    fp16* __restrict__ qh, fp16* __restrict__ kh, fp16* __restrict__ vh,
    int K)
{
    GEMM_PROLOG();
    const bool isQ = (blockIdx.x < 8);
    const int row0 = blockIdx.y * 128;
    const int col0 = (isQ ? blockIdx.x : (blockIdx.x - 8)) * 128;
    const fp16* src[2];
    src[0] = (isQ ? Aq : Akv) + (size_t)row0 * K;
    src[1] = (isQ ? Bq : Bkv) + (size_t)col0 * K;
    const int NS = K / 64;

    PDL_WAIT();             // both operands come from prep
    LOAD_SLAB(0, 0);
    GEMM_LOOP_BODY();

    const float oscl = isQ ? (0.125f * 1.44269504f) : 1.0f;
    const int qr = lid >> 2;
    const int qc = (lid & 3) * 2;
#pragma unroll
    for (int mi = 0; mi < 4; mi++) {
#pragma unroll
        for (int ni = 0; ni < 4; ni++) {
            const int n = col0 + warp_n * 32 + ni * 8 + qc;
            fp16* dst; const float* bp; int nn;
            if (isQ)           { dst = qh; bp = bq; nn = n; }
            else if (n < BDIM) { dst = kh; bp = bk; nn = n; }
            else               { dst = vh; bp = bv; nn = n - BDIM; }
            const float b0 = bp[nn], b1 = bp[nn + 1];
#pragma unroll
            for (int half = 0; half < 2; half++) {
                const int m = row0 + warp_m * 64 + mi * 16 + qr + half * 8;
                float v0 = (acc[mi][ni][half * 2 + 0] + b0) * oscl;
                float v1 = (acc[mi][ni][half * 2 + 1] + b1) * oscl;
                int hh = nn >> 6, dk = nn & 63, bb = m >> 11, ss = m & 2047;
                size_t o = (((size_t)(bb * NH + hh)) * SEQ + ss) * DKH + dk;
                *(__half2*)&dst[o] = __floats2half2_rn(v0, v1);
            }
        }
    }
}

// ======================= tensor-core flash attention (fp16, KV tile 128) =======================
#define AT_STRIDE 144
#define AT_KTILE  (128 * AT_STRIDE)           // 18432 B per 128x64 fp16 tile
#define AT_STAGE  (2 * AT_KTILE)              // K + V = 36864
#define AT_MSKOFF (2 * AT_STAGE)              // 73728
#define AT_SMEM   (AT_MSKOFF + 2 * 512 + 128)

__global__ __launch_bounds__(256, 2) void attn_tc(
    const fp16* __restrict__ Qg, const fp16* __restrict__ Kg,
    const fp16* __restrict__ Vg, const int* __restrict__ mask,
    fp16* __restrict__ O_out)
{
    extern __shared__ char sm[];
    const uint32_t smb = smem_u32(sm);
    const int tid = threadIdx.x;
    const int wid = tid >> 5;
    const int lid = tid & 31;
    const int q0  = blockIdx.x * 128;
    const int h   = blockIdx.y;
    const int bz  = blockIdx.z;
    const size_t hoff = ((size_t)(bz * NH + h)) * SEQ * DKH;

    const uint32_t lr   = (uint32_t)(lid & 15);
    const uint32_t lc16 = (uint32_t)(lid >> 4) * 16;

    PDL_WAIT();   // Q/K/V all produced by the QKV GEMM

    // ---- Q tile -> smem, then register fragments ----
    {
        const fp16* qh = Qg + hoff + (size_t)q0 * DKH;
#pragma unroll
        for (int u = 0; u < 4; u++) {
            int p = tid + u * 256;
            int r = p >> 3, c = p & 7;
            cp16(smb + (uint32_t)(r * AT_STRIDE + c * 16), qh + (size_t)r * DKH + c * 8);
        }
        CP_COMMIT(); CP_WAIT0();
    }
    __syncthreads();
    uint32_t qf[4][4];
#pragma unroll
    for (int ks = 0; ks < 4; ks++) {
        uint32_t ra = (uint32_t)((wid * 16 + lr) * AT_STRIDE) + ks * 32 + lc16;
        ldm_x4(qf[ks][0], qf[ks][1], qf[ks][2], qf[ks][3], smb + ra);
    }
    __syncthreads();

    float O[8][4];
#pragma unroll
    for (int i = 0; i < 8; i++)
#pragma unroll
        for (int j = 0; j < 4; j++) O[i][j] = 0.f;
    float m0 = -INFINITY, m1 = -INFINITY, l0 = 0.f, l1 = 0.f;

    const fp16* kg = Kg + hoff;
    const fp16* vg = Vg + hoff;
    const int*  mkg = mask + bz * SEQ;

#define LOAD_KV(ST, T) do {                                                     \
        const uint32_t _sb = smb + (ST) * AT_STAGE;                             \
        const int _k0 = (T) * 128;                                              \
        _Pragma("unroll")                                                       \
        for (int u = 0; u < 4; u++) {                                           \
            int p = tid + u * 256;                                              \
            int r = p >> 3, c = p & 7;                                          \
            uint32_t so = (uint32_t)(r * AT_STRIDE + c * 16);                   \
            size_t go = (size_t)(_k0 + r) * DKH + c * 8;                        \
            cp16(_sb + so, kg + go);                                            \
            cp16(_sb + AT_KTILE + so, vg + go);                                 \
        }                                                                       \
        if (tid < 32) cp16(smb + AT_MSKOFF + (ST) * 512 + tid * 16, mkg + _k0 + tid * 4); \
        CP_COMMIT();                                                            \
    } while (0)

    LOAD_KV(0, 0);

    for (int t = 0; t < SEQ / 128; t++) {
        const int st = t & 1;
        if (t + 1 < SEQ / 128) { LOAD_KV(st ^ 1, t + 1); CP_WAIT1(); }
        else                   { CP_WAIT0(); }

        const uint32_t kb = smb + st * AT_STAGE;
        const uint32_t vb = kb + AT_KTILE;
        const int* msk = (const int*)(sm + AT_MSKOFF + st * 512);

        const int allv = __syncthreads_and((int)(msk[tid & 127] != 0));

#pragma unroll
        for (int hf = 0; hf < 2; hf++) {
            const int kr0 = hf * 64;

            float s[8][4];
#pragma unroll
            for (int i = 0; i < 8; i++)
#pragma unroll
                for (int j = 0; j < 4; j++) s[i][j] = 0.f;

#pragma unroll
            for (int ks = 0; ks < 4; ks++) {
                const uint32_t koff = ks * 32 + lc16;
#pragma unroll
                for (int g = 0; g < 4; g++) {
                    uint32_t rb = (uint32_t)((kr0 + g * 16 + lr) * AT_STRIDE) + koff;
                    uint32_t r0, r1, r2, r3;
                    ldm_x4(r0, r1, r2, r3, kb + rb);
                    uint32_t b0[2] = {r0, r2}, b1[2] = {r1, r3};
                    mma16816(s[2 * g],     qf[ks], b0);
                    mma16816(s[2 * g + 1], qf[ks], b1);
                }
            }

            if (!allv) {
#pragma unroll
                for (int j = 0; j < 8; j++) {
                    int c0 = kr0 + j * 8 + (lid & 3) * 2;
                    bool z0 = (msk[c0] == 0), z1 = (msk[c0 + 1] == 0);
                    if (z0) { s[j][0] = -1e9f; s[j][2] = -1e9f; }
                    if (z1) { s[j][1] = -1e9f; s[j][3] = -1e9f; }
                }
            }

            // ---- online softmax, exp2 domain, f16x2 MUFU ----
            float mx0 = -INFINITY, mx1 = -INFINITY;
#pragma unroll
            for (int j = 0; j < 8; j++) {
                mx0 = fmaxf(mx0, fmaxf(s[j][0], s[j][1]));
                mx1 = fmaxf(mx1, fmaxf(s[j][2], s[j][3]));
            }
#pragma unroll
            for (int off = 1; off <= 2; off <<= 1) {
                mx0 = fmaxf(mx0, __shfl_xor_sync(0xffffffffu, mx0, off));
                mx1 = fmaxf(mx1, __shfl_xor_sync(0xffffffffu, mx1, off));
            }
            float nm0 = fmaxf(m0, mx0), nm1 = fmaxf(m1, mx1);
            uint32_t p01[8], p23[8];
            float sum0 = 0.f, sum1 = 0.f;
#pragma unroll
            for (int j = 0; j < 8; j++) {
                p01[j] = ex2_h2(cvt2(s[j][0] - nm0, s[j][1] - nm0));
                p23[j] = ex2_h2(cvt2(s[j][2] - nm1, s[j][3] - nm1));
                float2 f01 = __half22float2(*(__half2*)&p01[j]);
                float2 f23 = __half22float2(*(__half2*)&p23[j]);
                sum0 += f01.x + f01.y;
                sum1 += f23.x + f23.y;
            }
#pragma unroll
            for (int off = 1; off <= 2; off <<= 1) {
                sum0 += __shfl_xor_sync(0xffffffffu, sum0, off);
                sum1 += __shfl_xor_sync(0xffffffffu, sum1, off);
            }
            const bool same = (nm0 == m0) && (nm1 == m1);
            if (__all_sync(0xffffffffu, same)) {
                l0 += sum0; l1 += sum1;
            } else {
                // rescale factors: exponent must be (old_max - new_max) <= 0
                const float a0 = ex2f(m0 - nm0);   // ex2(-inf) = 0 on first tile
                const float a1 = ex2f(m1 - nm1);
                l0 = l0 * a0 + sum0;
                l1 = l1 * a1 + sum1;
                m0 = nm0; m1 = nm1;
#pragma unroll
                for (int i = 0; i < 8; i++) {
                    O[i][0] *= a0; O[i][1] *= a0;
                    O[i][2] *= a1; O[i][3] *= a1;
                }
            }

            // ---- O += P @ V (P already packed fp16) ----
#pragma unroll
            for (int j = 0; j < 4; j++) {
                uint32_t P[4];
                P[0] = p01[2 * j];
                P[1] = p23[2 * j];
                P[2] = p01[2 * j + 1];
                P[3] = p23[2 * j + 1];
#pragma unroll
                for (int c = 0; c < 4; c++) {
                    uint32_t r0, r1, r2, r3;
                    ldm_x4_t(r0, r1, r2, r3,
                             vb + (uint32_t)((kr0 + j * 16 + lr) * AT_STRIDE) + c * 32 + lc16);
                    uint32_t B0[2] = {r0, r1}, B1[2] = {r2, r3};
                    mma16816(O[2 * c],     P, B0);
                    mma16816(O[2 * c + 1], P, B1);
                }
            }
        }
        __syncthreads();
    }

    const float il0 = 1.f / (l0 > 0.f ? l0 : 1.f);
    const float il1 = 1.f / (l1 > 0.f ? l1 : 1.f);
    const int qr  = q0 + wid * 16 + (lid >> 2);
    const int col0 = h * DKH + (lid & 3) * 2;
#pragma unroll
    for (int nt = 0; nt < 8; nt++) {
        const int col = col0 + nt * 8;
        {
            __half2 p = __floats2half2_rn(O[nt][0] * il0, O[nt][1] * il0);
            *(__half2*)&O_out[((size_t)bz * SEQ + qr) * BDIM + col] = p;
        }
        {
            __half2 p = __floats2half2_rn(O[nt][2] * il1, O[nt][3] * il1);
            *(__half2*)&O_out[((size_t)bz * SEQ + qr + 8) * BDIM + col] = p;
        }
    }
}

// ======================= unified prep: 6 weight transposes + 2 activation converts =======================
__global__ __launch_bounds__(256) void prep_kernel(
    const float* __restrict__ Wq, const float* __restrict__ Wk,
    const float* __restrict__ Wv, const float* __restrict__ Wo,
    const float* __restrict__ W1g, const float* __restrict__ W2g,
    const float* __restrict__ Xg, const float* __restrict__ Yg,
    fp16* __restrict__ Tq, fp16* __restrict__ Tkv, fp16* __restrict__ To,
    fp16* __restrict__ T1, fp16* __restrict__ T2,
    fp16* __restrict__ HX, fp16* __restrict__ HY)
{
    __shared__ float t[32][33];
    const int z = blockIdx.z;
    const int tid = threadIdx.x;

    if (z >= 6) {
        const float* S = (z == 6) ? Xg : Yg;
        fp16* Dd = (z == 6) ? HX : HY;
        const int i = ((blockIdx.y * 128 + blockIdx.x) * 256 + tid) * 4;
        const float4 v = *(const float4*)(S + i);
        *(__half2*)(Dd + i)     = __floats2half2_rn(v.x, v.y);
        *(__half2*)(Dd + i + 2) = __floats2half2_rn(v.z, v.w);
        return;
    }

    const float* W; fp16* T; int K, N, n0, k0;
    if (z < 4) {
        if (blockIdx.x >= 32) return;
        W = (z == 0) ? Wq : (z == 1) ? Wk : (z == 2) ? Wv : Wo;
        T = (z == 0) ? Tq : (z == 1) ? Tkv : (z == 2) ? (Tkv + (size_t)BDIM * BDIM) : To;
        K = BDIM; N = BDIM;
        n0 = blockIdx.x * 32; k0 = blockIdx.y * 32;
    } else if (z == 4) {
        W = W1g; T = T1; K = BDIM; N = HIDN;
        n0 = blockIdx.x * 32; k0 = blockIdx.y * 32;
    } else {
        W = W2g; T = T2; K = HIDN; N = BDIM;
        n0 = blockIdx.y * 32; k0 = blockIdx.x * 32;
    }
    const int tx = tid & 31, ty = tid >> 5;
#pragma unroll
    for (int j = 0; j < 4; j++)
        t[ty + j * 8][tx] = W[(size_t)(k0 + ty + j * 8) * N + n0 + tx];
    __syncthreads();
#pragma unroll
    for (int j = 0; j < 4; j++)
        T[(size_t)(n0 + ty + j * 8) * K + k0 + tx] = __float2half(t[tx][ty + j * 8]);
}

// ======================= LayerNorm (+ optional fp16 output) =======================
__global__ __launch_bounds__(256) void ln_kernel(
    const float* __restrict__ X, const float* __restrict__ g,
    const float* __restrict__ b, float* __restrict__ Y, fp16* __restrict__ Yh)
{
    __shared__ float red[2][8];
    __shared__ float stats[2];
    const int row = blockIdx.x;
    const int tid = threadIdx.x;

    PDL_WAIT();

    const float4 v = ((const float4*)(X + (size_t)row * BDIM))[tid];
    float s = v.x + v.y + v.z + v.w;
    float q = v.x * v.x + v.y * v.y + v.z * v.z + v.w * v.w;
#pragma unroll
    for (int o = 16; o > 0; o >>= 1) {
        s += __shfl_xor_sync(0xffffffffu, s, o);
        q += __shfl_xor_sync(0xffffffffu, q, o);
    }
    const int lane = tid & 31, w = tid >> 5;
    if (lane == 0) { red[0][w] = s; red[1][w] = q; }
    __syncthreads();
    if (tid < 32) {
        s = (tid < 8) ? red[0][tid] : 0.f;
        q = (tid < 8) ? red[1][tid] : 0.f;
#pragma unroll
        for (int o = 4; o > 0; o >>= 1) {
            s += __shfl_xor_sync(0xffffffffu, s, o);
            q += __shfl_xor_sync(0xffffffffu, q, o);
        }
        if (tid == 0) {
            float mean = s * (1.f / BDIM);
            stats[0] = mean;
            stats[1] = rsqrtf(q * (1.f / BDIM) - mean * mean + 1e-5f);
        }
    }
    __syncthreads();
    const float mean = stats[0], rinv = stats[1];
    const float4 gg = ((const float4*)g)[tid];
    const float4 bb = ((const float4*)b)[tid];
    float4 o4;
    o4.x = (v.x - mean) * rinv * gg.x + bb.x;
    o4.y = (v.y - mean) * rinv * gg.y + bb.y;
    o4.z = (v.z - mean) * rinv * gg.z + bb.z;
    o4.w = (v.w - mean) * rinv * gg.w + bb.w;
    if (Y) ((float4*)(Y + (size_t)row * BDIM))[tid] = o4;
    if (Yh) {
        size_t base = (size_t)row * BDIM + tid * 4;
        *(__half2*)(Yh + base)     = __floats2half2_rn(o4.x, o4.y);
        *(__half2*)(Yh + base + 2) = __floats2half2_rn(o4.z, o4.w);
    }
}

// ======================= launcher =======================
extern "C" void kernel_launch(void* const* d_in, const int* in_sizes, int n_in,
                              void* d_out, int out_size)
{
    const float* x    = (const float*)d_in[0];
    const float* y    = (const float*)d_in[1];
    const int*   mask = (const int*)  d_in[2];
    const float* Wq = (const float*)d_in[3];  const float* bq = (const float*)d_in[4];
    const float* Wk = (const float*)d_in[5];  const float* bk = (const float*)d_in[6];
    const float* Wv = (const float*)d_in[7];  const float* bv = (const float*)d_in[8];
    const float* Wo = (const float*)d_in[9];  const float* bo = (const float*)d_in[10];
    const float* W1 = (const float*)d_in[11]; const float* b1 = (const float*)d_in[12];
    const float* W2 = (const float*)d_in[13]; const float* b2 = (const float*)d_in[14];
    const float* g1 = (const float*)d_in[15]; const float* be1 = (const float*)d_in[16];
    const float* g2 = (const float*)d_in[17]; const float* be2 = (const float*)d_in[18];
    float* out = (float*)d_out;

    float *s1p, *x1p, *s2p;
    fp16 *xh, *yh, *qh, *kh, *vh, *ah, *x1h, *hh;
    fp16 *wq, *wkv, *wo, *w1, *w2;
    cudaGetSymbolAddress((void**)&s1p, g_s1);  cudaGetSymbolAddress((void**)&x1p, g_x1);
    cudaGetSymbolAddress((void**)&s2p, g_s2);
    cudaGetSymbolAddress((void**)&xh, g_xh);   cudaGetSymbolAddress((void**)&yh, g_yh);
    cudaGetSymbolAddress((void**)&qh, g_Qh);   cudaGetSymbolAddress((void**)&kh, g_Kh);
    cudaGetSymbolAddress((void**)&vh, g_Vh);   cudaGetSymbolAddress((void**)&ah, g_ah);
    cudaGetSymbolAddress((void**)&x1h, g_x1h); cudaGetSymbolAddress((void**)&hh, g_hh);
    cudaGetSymbolAddress((void**)&wq, g_wqT);  cudaGetSymbolAddress((void**)&wkv, g_wkvT);
    cudaGetSymbolAddress((void**)&wo, g_woT);
    cudaGetSymbolAddress((void**)&w1, g_w1T);  cudaGetSymbolAddress((void**)&w2, g_w2T);

    cudaFuncSetAttribute(mma_gemm, cudaFuncAttributeMaxDynamicSharedMemorySize, GEMM_SMEM);
    cudaFuncSetAttribute(mma_qkv,  cudaFuncAttributeMaxDynamicSharedMemorySize, GEMM_SMEM);
    cudaFuncSetAttribute(attn_tc,  cudaFuncAttributeMaxDynamicSharedMemorySize, AT_SMEM);

    // ---- prep: all 6 transposes + both activation converts in ONE launch ----
    prep_kernel<<<dim3(HIDN / 32, BDIM / 32, 8), 256>>>(
        Wq, Wk, Wv, Wo, W1, W2, x, y, wq, wkv, wo, w1, w2, xh, yh);

    // ---- PDL launch config ----
    cudaLaunchAttribute pdlAttr;
    pdlAttr.id = cudaLaunchAttributeProgrammaticStreamSerialization;
    pdlAttr.val.programmaticStreamSerializationAllowed = 1;
    cudaLaunchConfig_t cfg;
    memset(&cfg, 0, sizeof(cfg));
    cfg.blockDim = dim3(256, 1, 1);
    cfg.attrs = &pdlAttr;
    cfg.numAttrs = 1;
    cfg.stream = 0;

    dim3 gD(BDIM / 128, MROWS / 128);          // 8 x 32
    dim3 gQKV(3 * BDIM / 128, MROWS / 128);    // 24 x 32 = 768 CTAs
    dim3 gH(HIDN / 128, MROWS / 128);          // 32 x 32

    // fused QKV projections
    cfg.gridDim = gQKV; cfg.dynamicSmemBytes = GEMM_SMEM;
    cudaLaunchKernelEx(&cfg, mma_qkv, (const fp16*)xh, (const fp16*)yh,
                       (const fp16*)wq, (const fp16*)wkv, bq, bk, bv,
                       (fp16*)qh, (fp16*)kh, (fp16*)vh, (int)BDIM);

    // flash attention
    cfg.gridDim = dim3(SEQ / 128, NH, NB); cfg.dynamicSmemBytes = AT_SMEM;
    cudaLaunchKernelEx(&cfg, attn_tc, (const fp16*)qh, (const fp16*)kh,
                       (const fp16*)vh, mask, (fp16*)ah);

    // s1 = x + attn @ Wo + bo ; x1 = LN(s1) (+fp16)
    cfg.gridDim = gD; cfg.dynamicSmemBytes = GEMM_SMEM;
    cudaLaunchKernelEx(&cfg, mma_gemm, (const fp16*)ah, (const fp16*)wo, bo, x,
                       (float*)s1p, (fp16*)nullptr, (int)MROWS, (int)BDIM, (int)BDIM, (int)MODE_RES);
    cfg.gridDim = dim3(MROWS, 1, 1); cfg.dynamicSmemBytes = 0;
    cudaLaunchKernelEx(&cfg, ln_kernel, (const float*)s1p, g1, be1, (float*)x1p, (fp16*)x1h);

    // FFN
    cfg.gridDim = gH; cfg.dynamicSmemBytes = GEMM_SMEM;
    cudaLaunchKernelEx(&cfg, mma_gemm, (const fp16*)x1h, (const fp16*)w1, b1, (const float*)nullptr,
                       (float*)nullptr, (fp16*)hh, (int)MROWS, (int)HIDN, (int)BDIM, (int)MODE_RELU_H);
    cfg.gridDim = gD; cfg.dynamicSmemBytes = GEMM_SMEM;
    cudaLaunchKernelEx(&cfg, mma_gemm, (const fp16*)hh, (const fp16*)w2, b2, (const float*)x1p,
                       (float*)s2p, (fp16*)nullptr, (int)MROWS, (int)BDIM, (int)HIDN, (int)MODE_RES);
    cfg.gridDim = dim3(MROWS, 1, 1); cfg.dynamicSmemBytes = 0;
    cudaLaunchKernelEx(&cfg, ln_kernel, (const float*)s2p, g2, be2, out, (fp16*)nullptr);
}